// round 1
// baseline (speedup 1.0000x reference)
#include <cuda_runtime.h>
#include <math.h>
#include <stdint.h>

// Problem dims (fixed by the dataset)
#define B_   256
#define T_   256
#define D_   128
#define H_   512
#define G3H  1536
#define BT   (B_ * T_)

// ---------------------------------------------------------------------------
// Scratch (static device allocations; harness forbids cudaMalloc)
// ---------------------------------------------------------------------------
__device__ float g_xg[(size_t)BT * G3H];   // 402 MB: input-gate projections (reused for layer0 and layer1)
__device__ float g_y0[(size_t)BT * H_];    // 134 MB: layer0 outputs
__device__ float g_h[2][B_ * H_];          // double-buffered hidden state
__device__ unsigned g_bar_cnt;             // zero-initialized
__device__ volatile unsigned g_bar_gen;    // zero-initialized

// ---------------------------------------------------------------------------
// Software grid barrier (all blocks guaranteed co-resident: grid=128 <= 148 SMs,
// 1 block/SM by smem/regs).
// ---------------------------------------------------------------------------
__device__ __forceinline__ void grid_barrier(unsigned nb) {
    __syncthreads();
    if (threadIdx.x == 0) {
        __threadfence();
        unsigned gen = g_bar_gen;          // read BEFORE arriving
        if (atomicAdd(&g_bar_cnt, 1u) == nb - 1u) {
            atomicExch(&g_bar_cnt, 0u);
            __threadfence();
            g_bar_gen = gen + 1u;
        } else {
            while (g_bar_gen == gen) { __nanosleep(64); }
        }
        __threadfence();
    }
    __syncthreads();
}

// ---------------------------------------------------------------------------
// Generic tiled GEMM: C[M, 1536] = A[M, K] @ W[1536, K]^T + bias[1536]
// Writes into g_xg. BM=BN=64, BK=32, 256 threads, 4x4 per thread.
// Grid: (1536/64=24, M/64)
// ---------------------------------------------------------------------------
__global__ void __launch_bounds__(256) gemm_bias_kernel(
    const float* __restrict__ A, const float* __restrict__ W,
    const float* __restrict__ bias, int K)
{
    __shared__ float As[32][68];
    __shared__ float Bs[32][68];

    const int tid = threadIdx.x;
    const int m0 = blockIdx.y * 64;
    const int n0 = blockIdx.x * 64;
    const int ty = tid >> 4;
    const int tx = tid & 15;

    float acc[4][4] = {};

    for (int k0 = 0; k0 < K; k0 += 32) {
#pragma unroll
        for (int r = 0; r < 2; r++) {
            int f   = tid + r * 256;
            int row = f >> 3;
            int c4  = (f & 7) << 2;
            float4 va = *(const float4*)(A + (size_t)(m0 + row) * K + k0 + c4);
            As[c4 + 0][row] = va.x; As[c4 + 1][row] = va.y;
            As[c4 + 2][row] = va.z; As[c4 + 3][row] = va.w;
            float4 vb = *(const float4*)(W + (size_t)(n0 + row) * K + k0 + c4);
            Bs[c4 + 0][row] = vb.x; Bs[c4 + 1][row] = vb.y;
            Bs[c4 + 2][row] = vb.z; Bs[c4 + 3][row] = vb.w;
        }
        __syncthreads();

#pragma unroll
        for (int kk = 0; kk < 32; kk++) {
            float4 ra = *(const float4*)&As[kk][ty << 2];
            float4 rb = *(const float4*)&Bs[kk][tx << 2];
            float a0 = ra.x, a1 = ra.y, a2 = ra.z, a3 = ra.w;
            float b0 = rb.x, b1 = rb.y, b2 = rb.z, b3 = rb.w;
            acc[0][0] = fmaf(a0, b0, acc[0][0]); acc[0][1] = fmaf(a0, b1, acc[0][1]);
            acc[0][2] = fmaf(a0, b2, acc[0][2]); acc[0][3] = fmaf(a0, b3, acc[0][3]);
            acc[1][0] = fmaf(a1, b0, acc[1][0]); acc[1][1] = fmaf(a1, b1, acc[1][1]);
            acc[1][2] = fmaf(a1, b2, acc[1][2]); acc[1][3] = fmaf(a1, b3, acc[1][3]);
            acc[2][0] = fmaf(a2, b0, acc[2][0]); acc[2][1] = fmaf(a2, b1, acc[2][1]);
            acc[2][2] = fmaf(a2, b2, acc[2][2]); acc[2][3] = fmaf(a2, b3, acc[2][3]);
            acc[3][0] = fmaf(a3, b0, acc[3][0]); acc[3][1] = fmaf(a3, b1, acc[3][1]);
            acc[3][2] = fmaf(a3, b2, acc[3][2]); acc[3][3] = fmaf(a3, b3, acc[3][3]);
        }
        __syncthreads();
    }

    const int ncol = n0 + (tx << 2);
    float4 bv = *(const float4*)(bias + ncol);
#pragma unroll
    for (int i = 0; i < 4; i++) {
        int m = m0 + (ty << 2) + i;
        float4 o;
        o.x = acc[i][0] + bv.x; o.y = acc[i][1] + bv.y;
        o.z = acc[i][2] + bv.z; o.w = acc[i][3] + bv.w;
        *(float4*)(g_xg + (size_t)m * G3H + ncol) = o;
    }
}

// ---------------------------------------------------------------------------
// Persistent GRU recurrent kernel. grid = 128 blocks x 256 threads.
// Block (mt, jt): batch rows [mt*64, mt*64+64), hidden cols [jt*16, jt*16+16).
// Each block computes all 3 gate projections for its (m, j) tile, so the gate
// update is block-local; one grid barrier per time step (h double-buffered).
// ---------------------------------------------------------------------------
template<bool WRITE_Y>
__global__ void __launch_bounds__(256) gru_rec_kernel(
    const float* __restrict__ Whh, const float* __restrict__ bhh)
{
    __shared__ float Hs[64][68];       // h tile, [row][k]
    __shared__ float Ws[3][64][17];    // weight tile, [gate][k][j]  (pad 17 vs bank conflicts)

    const int tid = threadIdx.x;
    const int bid = blockIdx.x;
    const int jt = bid & 31, mt = bid >> 5;
    const int m0 = mt * 64, j0 = jt * 16;
    const int ty = tid >> 4, tx = tid & 15;
    const int ty4 = ty << 2;
    const int j = j0 + tx;

    // zero initial hidden state (buffer 0): 128 blocks * 256 thr * 4 = 131072 floats
    {
        float4 z = make_float4(0.f, 0.f, 0.f, 0.f);
        *(float4*)(&g_h[0][bid * 1024 + tid * 4]) = z;
    }

    // preload recurrent biases for this thread's column
    float bb0 = bhh[0 * H_ + j];
    float bb1 = bhh[1 * H_ + j];
    float bb2 = bhh[2 * H_ + j];

    grid_barrier(128);

    for (int t = 0; t < T_; t++) {
        const float* hin = g_h[t & 1];
        float* hout = g_h[(t + 1) & 1];

        float acc[3][4] = {};

        for (int k0 = 0; k0 < H_; k0 += 64) {
            // load h tile: 64 rows x 64 k = 1024 float4, 4 per thread
#pragma unroll
            for (int r = 0; r < 4; r++) {
                int f   = tid + r * 256;
                int row = f >> 4;
                int c4  = (f & 15) << 2;
                float4 v = *(const float4*)(hin + (size_t)(m0 + row) * H_ + k0 + c4);
                *(float4*)&Hs[row][c4] = v;
            }
            // load W tile: 3 gates x 16 j-rows x 64 k
            {
                int jj = tid >> 4;
                int c4 = (tid & 15) << 2;
#pragma unroll
                for (int g = 0; g < 3; g++) {
                    float4 w = *(const float4*)(Whh + (size_t)(g * H_ + j0 + jj) * H_ + k0 + c4);
                    Ws[g][c4 + 0][jj] = w.x; Ws[g][c4 + 1][jj] = w.y;
                    Ws[g][c4 + 2][jj] = w.z; Ws[g][c4 + 3][jj] = w.w;
                }
            }
            __syncthreads();

#pragma unroll 16
            for (int kk = 0; kk < 64; kk++) {
                float w0 = Ws[0][kk][tx];
                float w1 = Ws[1][kk][tx];
                float w2 = Ws[2][kk][tx];
#pragma unroll
                for (int i = 0; i < 4; i++) {
                    float hv = Hs[ty4 + i][kk];
                    acc[0][i] = fmaf(hv, w0, acc[0][i]);
                    acc[1][i] = fmaf(hv, w1, acc[1][i]);
                    acc[2][i] = fmaf(hv, w2, acc[2][i]);
                }
            }
            __syncthreads();
        }

        // gate update for this thread's 4 (m, j) elements
#pragma unroll
        for (int i = 0; i < 4; i++) {
            int m = m0 + ty4 + i;
            size_t xb = ((size_t)m * T_ + t) * G3H + j;
            float xr = g_xg[xb];
            float xz = g_xg[xb + H_];
            float xn = g_xg[xb + 2 * H_];

            float hr = acc[0][i] + bb0;
            float hz = acc[1][i] + bb1;
            float hn = acc[2][i] + bb2;

            float r = 1.0f / (1.0f + expf(-(xr + hr)));
            float z = 1.0f / (1.0f + expf(-(xz + hz)));
            float n = tanhf(xn + r * hn);

            float hold = hin[(size_t)m * H_ + j];
            float hnew = (1.0f - z) * n + z * hold;

            hout[(size_t)m * H_ + j] = hnew;
            if (WRITE_Y) {
                g_y0[((size_t)m * T_ + t) * H_ + j] = hnew;
            }
        }

        grid_barrier(128);
    }
}

// ---------------------------------------------------------------------------
// Head: out = relu(relu(hT) @ fc1^T + b1) @ fc2^T + b2
// grid = 256 (batch), 128 threads. Final hidden lives in g_h[0] (T=256 even).
// ---------------------------------------------------------------------------
__global__ void __launch_bounds__(128) head_kernel(
    const float* __restrict__ w1, const float* __restrict__ b1,
    const float* __restrict__ w2, const float* __restrict__ b2,
    float* __restrict__ out)
{
    __shared__ float sh[H_];
    __shared__ float s1[128];
    const int b = blockIdx.x;
    const int tid = threadIdx.x;

#pragma unroll
    for (int r = 0; r < 4; r++) {
        float v = g_h[0][(size_t)b * H_ + tid + r * 128];
        sh[tid + r * 128] = fmaxf(v, 0.0f);
    }
    __syncthreads();

    float acc = b1[tid];
    const float* wrow = w1 + (size_t)tid * H_;
#pragma unroll 8
    for (int jj = 0; jj < H_; jj++) acc = fmaf(sh[jj], __ldg(wrow + jj), acc);
    s1[tid] = fmaxf(acc, 0.0f);
    __syncthreads();

    if (tid < 10) {
        float a = b2[tid];
        const float* w2row = w2 + (size_t)tid * 128;
#pragma unroll 8
        for (int i = 0; i < 128; i++) a = fmaf(s1[i], __ldg(w2row + i), a);
        out[(size_t)b * 10 + tid] = a;
    }
}

// ---------------------------------------------------------------------------
// Launch
// ---------------------------------------------------------------------------
extern "C" void kernel_launch(void* const* d_in, const int* in_sizes, int n_in,
                              void* d_out, int out_size)
{
    const float* x    = (const float*)d_in[0];
    const float* Wih0 = (const float*)d_in[1];
    const float* Whh0 = (const float*)d_in[2];
    const float* bih0 = (const float*)d_in[3];
    const float* bhh0 = (const float*)d_in[4];
    const float* Wih1 = (const float*)d_in[5];
    const float* Whh1 = (const float*)d_in[6];
    const float* bih1 = (const float*)d_in[7];
    const float* bhh1 = (const float*)d_in[8];
    const float* fc1w = (const float*)d_in[9];
    const float* fc1b = (const float*)d_in[10];
    const float* fc2w = (const float*)d_in[11];
    const float* fc2b = (const float*)d_in[12];
    float* out = (float*)d_out;

    float* y0_ptr = nullptr;
    cudaGetSymbolAddress((void**)&y0_ptr, g_y0);

    dim3 gemm_grid(G3H / 64, BT / 64);

    // Phase 1: xg0 = x @ W_ih0^T + b_ih0   (K = 128)
    gemm_bias_kernel<<<gemm_grid, 256>>>(x, Wih0, bih0, D_);

    // Phase 2: layer-0 recurrence, writes y0
    gru_rec_kernel<true><<<128, 256>>>(Whh0, bhh0);

    // Phase 3: xg1 = y0 @ W_ih1^T + b_ih1  (K = 512), overwrites g_xg
    gemm_bias_kernel<<<gemm_grid, 256>>>(y0_ptr, Wih1, bih1, H_);

    // Phase 4: layer-1 recurrence, final hidden in g_h[0]
    gru_rec_kernel<false><<<128, 256>>>(Whh1, bhh1);

    // Phase 5: MLP head
    head_kernel<<<B_, 128>>>(fc1w, fc1b, fc2w, fc2b, out);
}

// round 2
// speedup vs baseline: 1.2607x; 1.2607x over previous
#include <cuda_runtime.h>
#include <math.h>
#include <stdint.h>

// Problem dims (fixed by the dataset)
#define B_   256
#define T_   256
#define D_   128
#define H_   512
#define G3H  1536
#define BT   (B_ * T_)

// ---------------------------------------------------------------------------
// Scratch (static device allocations; harness forbids cudaMalloc)
// ---------------------------------------------------------------------------
__device__ float g_xg[(size_t)BT * G3H];   // 402 MB: input-gate projections
__device__ float g_y0[(size_t)BT * H_];    // 134 MB: layer0 outputs
__device__ float g_h[2][B_ * H_];          // double-buffered hidden state
__device__ unsigned g_bar_cnt;
__device__ volatile unsigned g_bar_gen;

// ---------------------------------------------------------------------------
// Software grid barrier (128 blocks, all co-resident: 1 block/SM by smem)
// ---------------------------------------------------------------------------
__device__ __forceinline__ void grid_barrier(unsigned nb) {
    __syncthreads();
    if (threadIdx.x == 0) {
        __threadfence();
        unsigned gen = g_bar_gen;
        if (atomicAdd(&g_bar_cnt, 1u) == nb - 1u) {
            atomicExch(&g_bar_cnt, 0u);
            __threadfence();
            g_bar_gen = gen + 1u;
        } else {
            while (g_bar_gen == gen) { __nanosleep(64); }
        }
        __threadfence();
    }
    __syncthreads();
}

// ---------------------------------------------------------------------------
// tf32 helpers
// ---------------------------------------------------------------------------
__device__ __forceinline__ uint32_t f2tf(float f) {
    uint32_t u;
    asm("cvt.rna.tf32.f32 %0, %1;" : "=r"(u) : "f"(f));
    return u;
}

__device__ __forceinline__ void mma_tf32(float* c, const uint32_t* a, const uint32_t* b) {
    asm volatile(
        "mma.sync.aligned.m16n8k8.row.col.f32.tf32.tf32.f32 "
        "{%0,%1,%2,%3}, {%4,%5,%6,%7}, {%8,%9}, {%0,%1,%2,%3};\n"
        : "+f"(c[0]), "+f"(c[1]), "+f"(c[2]), "+f"(c[3])
        : "r"(a[0]), "r"(a[1]), "r"(a[2]), "r"(a[3]), "r"(b[0]), "r"(b[1]));
}

// ---------------------------------------------------------------------------
// tf32 tensor-core GEMM: C[M, 1536] = A[M, K] @ W[1536, K]^T + bias
// Block tile 128(M) x 128(N) x 32(K), 256 threads = 8 warps (2x4),
// warp tile 64(M) x 32(N) = 4x4 m16n8k8 tiles.
// Grid: (1536/128=12, M/128)
// ---------------------------------------------------------------------------
__global__ void __launch_bounds__(256) gemm_tf32_kernel(
    const float* __restrict__ A, const float* __restrict__ W,
    const float* __restrict__ bias, int K, float* __restrict__ C)
{
    __shared__ uint32_t As[128][36];   // padded: conflict-free frag loads
    __shared__ uint32_t Bs[128][36];   // rows = n, cols = k

    const int tid  = threadIdx.x;
    const int m0   = blockIdx.y * 128;
    const int n0   = blockIdx.x * 128;
    const int warp = tid >> 5, lane = tid & 31;
    const int wm = warp >> 2, wn = warp & 3;     // 2 x 4 warp grid
    const int g  = lane >> 2, tg = lane & 3;

    float acc[4][4][4] = {};   // [mtile][ntile][c0..c3]

    for (int k0 = 0; k0 < K; k0 += 32) {
        // Load A tile (128x32) and W tile (128x32), converting to tf32.
#pragma unroll
        for (int r = 0; r < 4; r++) {
            int f   = tid + (r << 8);      // 0..1023
            int row = f >> 3;              // 0..127
            int c4  = (f & 7) << 2;        // 0..28
            float4 va = *(const float4*)(A + (size_t)(m0 + row) * K + k0 + c4);
            As[row][c4 + 0] = f2tf(va.x);
            As[row][c4 + 1] = f2tf(va.y);
            As[row][c4 + 2] = f2tf(va.z);
            As[row][c4 + 3] = f2tf(va.w);
            float4 vb = *(const float4*)(W + (size_t)(n0 + row) * K + k0 + c4);
            Bs[row][c4 + 0] = f2tf(vb.x);
            Bs[row][c4 + 1] = f2tf(vb.y);
            Bs[row][c4 + 2] = f2tf(vb.z);
            Bs[row][c4 + 3] = f2tf(vb.w);
        }
        __syncthreads();

#pragma unroll
        for (int s = 0; s < 4; s++) {
            const int kb = s << 3;
            uint32_t a[4][4], b[4][2];
#pragma unroll
            for (int i = 0; i < 4; i++) {
                int r0 = wm * 64 + i * 16 + g;
                a[i][0] = As[r0][kb + tg];
                a[i][1] = As[r0 + 8][kb + tg];
                a[i][2] = As[r0][kb + tg + 4];
                a[i][3] = As[r0 + 8][kb + tg + 4];
            }
#pragma unroll
            for (int j = 0; j < 4; j++) {
                int c = wn * 32 + j * 8 + g;
                b[j][0] = Bs[c][kb + tg];
                b[j][1] = Bs[c][kb + tg + 4];
            }
#pragma unroll
            for (int i = 0; i < 4; i++)
#pragma unroll
                for (int j = 0; j < 4; j++)
                    mma_tf32(acc[i][j], a[i], b[j]);
        }
        __syncthreads();
    }

    // Epilogue: += bias, write fp32
#pragma unroll
    for (int i = 0; i < 4; i++) {
        int r0 = m0 + wm * 64 + i * 16 + g;
#pragma unroll
        for (int j = 0; j < 4; j++) {
            int col = n0 + wn * 32 + j * 8 + tg * 2;
            float2 bv = *(const float2*)(bias + col);
            float2 o0 = make_float2(acc[i][j][0] + bv.x, acc[i][j][1] + bv.y);
            float2 o1 = make_float2(acc[i][j][2] + bv.x, acc[i][j][3] + bv.y);
            *(float2*)(C + (size_t)r0 * G3H + col)       = o0;
            *(float2*)(C + (size_t)(r0 + 8) * G3H + col) = o1;
        }
    }
}

// ---------------------------------------------------------------------------
// Persistent GRU recurrent kernel. grid = 128 blocks x 256 threads.
// Block (mt, jt): batch rows [mt*64, +64), hidden cols [jt*16, +16).
// W_hh tile (3 x 16 x 512 = 96KB) cached in smem for ALL 256 steps.
// h-chunk tile double-buffered: one __syncthreads per chunk.
// ---------------------------------------------------------------------------
template<bool WRITE_Y>
__global__ void __launch_bounds__(256) gru_rec_kernel(
    const float* __restrict__ Whh, const float* __restrict__ bhh)
{
    extern __shared__ float sm[];
    float* Wsm = sm;                       // [3][512][16] = 24576 floats (96KB)
    float* Hsm = sm + 3 * 512 * 16;        // 2 x [64][68] = 8704 floats (34KB)

    const int tid = threadIdx.x;
    const int bid = blockIdx.x;
    const int jt = bid & 31, mt = bid >> 5;
    const int m0 = mt * 64, j0 = jt * 16;
    const int ty = tid >> 4, tx = tid & 15;
    const int ty4 = ty << 2;
    const int j = j0 + tx;

    // Preload W_hh tile into smem once: layout Wsm[g*8192 + k*16 + jj]
    for (int f = tid; f < 6144; f += 256) {
        int kq = (f & 127) << 2;           // k quad start
        int gj = f >> 7;                   // 0..47
        int gg = gj >> 4, jj = gj & 15;
        float4 w = *(const float4*)(Whh + ((size_t)(gg * H_ + j0 + jj)) * H_ + kq);
        float* dst = Wsm + gg * 8192 + jj;
        dst[(kq + 0) * 16] = w.x;
        dst[(kq + 1) * 16] = w.y;
        dst[(kq + 2) * 16] = w.z;
        dst[(kq + 3) * 16] = w.w;
    }

    // zero initial hidden state (buffer 0)
    {
        float4 z = make_float4(0.f, 0.f, 0.f, 0.f);
        *(float4*)(&g_h[0][bid * 1024 + tid * 4]) = z;
    }

    float bb0 = bhh[0 * H_ + j];
    float bb1 = bhh[1 * H_ + j];
    float bb2 = bhh[2 * H_ + j];

    grid_barrier(128);

    for (int t = 0; t < T_; t++) {
        const float* hin = g_h[t & 1];
        float* hout = g_h[(t + 1) & 1];

        float acc[3][4] = {};

        for (int ch = 0; ch < 8; ch++) {
            const int k0 = ch << 6;
            float* hs = Hsm + (ch & 1) * (64 * 68);
            // load h chunk (64 rows x 64 k)
#pragma unroll
            for (int r = 0; r < 4; r++) {
                int f   = tid + (r << 8);
                int row = f >> 4;
                int c4  = (f & 15) << 2;
                *(float4*)(hs + row * 68 + c4) =
                    *(const float4*)(hin + (size_t)(m0 + row) * H_ + k0 + c4);
            }
            __syncthreads();   // double-buffer: single sync per chunk is safe

            const float* wk  = Wsm + k0 * 16 + tx;
            const float* h0p = hs + ty4 * 68;
#pragma unroll 16
            for (int kk = 0; kk < 64; kk++) {
                float w0 = wk[kk * 16];
                float w1 = wk[kk * 16 + 8192];
                float w2 = wk[kk * 16 + 16384];
                float hv0 = h0p[kk];
                float hv1 = h0p[68 + kk];
                float hv2 = h0p[136 + kk];
                float hv3 = h0p[204 + kk];
                acc[0][0] = fmaf(hv0, w0, acc[0][0]);
                acc[1][0] = fmaf(hv0, w1, acc[1][0]);
                acc[2][0] = fmaf(hv0, w2, acc[2][0]);
                acc[0][1] = fmaf(hv1, w0, acc[0][1]);
                acc[1][1] = fmaf(hv1, w1, acc[1][1]);
                acc[2][1] = fmaf(hv1, w2, acc[2][1]);
                acc[0][2] = fmaf(hv2, w0, acc[0][2]);
                acc[1][2] = fmaf(hv2, w1, acc[1][2]);
                acc[2][2] = fmaf(hv2, w2, acc[2][2]);
                acc[0][3] = fmaf(hv3, w0, acc[0][3]);
                acc[1][3] = fmaf(hv3, w1, acc[1][3]);
                acc[2][3] = fmaf(hv3, w2, acc[2][3]);
            }
        }

        // gate update for this thread's 4 (m, j) elements
#pragma unroll
        for (int i = 0; i < 4; i++) {
            int m = m0 + ty4 + i;
            size_t xb = ((size_t)m * T_ + t) * G3H + j;
            float xr = g_xg[xb];
            float xz = g_xg[xb + H_];
            float xn = g_xg[xb + 2 * H_];

            float hr = acc[0][i] + bb0;
            float hz = acc[1][i] + bb1;
            float hn = acc[2][i] + bb2;

            float r = 1.0f / (1.0f + expf(-(xr + hr)));
            float z = 1.0f / (1.0f + expf(-(xz + hz)));
            float n = tanhf(xn + r * hn);

            float hold = hin[(size_t)m * H_ + j];
            float hnew = (1.0f - z) * n + z * hold;

            hout[(size_t)m * H_ + j] = hnew;
            if (WRITE_Y) {
                g_y0[((size_t)m * T_ + t) * H_ + j] = hnew;
            }
        }

        grid_barrier(128);
    }
}

// ---------------------------------------------------------------------------
// Head: out = relu(relu(hT) @ fc1^T + b1) @ fc2^T + b2
// ---------------------------------------------------------------------------
__global__ void __launch_bounds__(128) head_kernel(
    const float* __restrict__ w1, const float* __restrict__ b1,
    const float* __restrict__ w2, const float* __restrict__ b2,
    float* __restrict__ out)
{
    __shared__ float sh[H_];
    __shared__ float s1[128];
    const int b = blockIdx.x;
    const int tid = threadIdx.x;

#pragma unroll
    for (int r = 0; r < 4; r++) {
        float v = g_h[0][(size_t)b * H_ + tid + r * 128];
        sh[tid + r * 128] = fmaxf(v, 0.0f);
    }
    __syncthreads();

    float acc = b1[tid];
    const float* wrow = w1 + (size_t)tid * H_;
#pragma unroll 8
    for (int jj = 0; jj < H_; jj++) acc = fmaf(sh[jj], __ldg(wrow + jj), acc);
    s1[tid] = fmaxf(acc, 0.0f);
    __syncthreads();

    if (tid < 10) {
        float a = b2[tid];
        const float* w2row = w2 + (size_t)tid * 128;
#pragma unroll 8
        for (int i = 0; i < 128; i++) a = fmaf(s1[i], __ldg(w2row + i), a);
        out[(size_t)b * 10 + tid] = a;
    }
}

// ---------------------------------------------------------------------------
// Launch
// ---------------------------------------------------------------------------
extern "C" void kernel_launch(void* const* d_in, const int* in_sizes, int n_in,
                              void* d_out, int out_size)
{
    const float* x    = (const float*)d_in[0];
    const float* Wih0 = (const float*)d_in[1];
    const float* Whh0 = (const float*)d_in[2];
    const float* bih0 = (const float*)d_in[3];
    const float* bhh0 = (const float*)d_in[4];
    const float* Wih1 = (const float*)d_in[5];
    const float* Whh1 = (const float*)d_in[6];
    const float* bih1 = (const float*)d_in[7];
    const float* bhh1 = (const float*)d_in[8];
    const float* fc1w = (const float*)d_in[9];
    const float* fc1b = (const float*)d_in[10];
    const float* fc2w = (const float*)d_in[11];
    const float* fc2b = (const float*)d_in[12];
    float* out = (float*)d_out;

    float* y0_ptr = nullptr;
    float* xg_ptr = nullptr;
    cudaGetSymbolAddress((void**)&y0_ptr, g_y0);
    cudaGetSymbolAddress((void**)&xg_ptr, g_xg);

    const int rec_smem = (3 * 512 * 16 + 2 * 64 * 68) * (int)sizeof(float); // 133120
    cudaFuncSetAttribute((const void*)gru_rec_kernel<true>,
                         cudaFuncAttributeMaxDynamicSharedMemorySize, rec_smem);
    cudaFuncSetAttribute((const void*)gru_rec_kernel<false>,
                         cudaFuncAttributeMaxDynamicSharedMemorySize, rec_smem);

    dim3 gemm_grid(G3H / 128, BT / 128);  // (12, 512)

    // Phase 1: xg0 = x @ W_ih0^T + b_ih0   (K = 128)
    gemm_tf32_kernel<<<gemm_grid, 256>>>(x, Wih0, bih0, D_, xg_ptr);

    // Phase 2: layer-0 recurrence, writes y0
    gru_rec_kernel<true><<<128, 256, rec_smem>>>(Whh0, bhh0);

    // Phase 3: xg1 = y0 @ W_ih1^T + b_ih1  (K = 512)
    gemm_tf32_kernel<<<gemm_grid, 256>>>(y0_ptr, Wih1, bih1, H_, xg_ptr);

    // Phase 4: layer-1 recurrence
    gru_rec_kernel<false><<<128, 256, rec_smem>>>(Whh1, bhh1);

    // Phase 5: MLP head
    head_kernel<<<B_, 128>>>(fc1w, fc1b, fc2w, fc2b, out);
}

// round 3
// speedup vs baseline: 2.9281x; 2.3227x over previous
#include <cuda_runtime.h>
#include <cuda_bf16.h>
#include <math.h>
#include <stdint.h>

// Problem dims (fixed by the dataset)
#define B_   256
#define T_   256
#define D_   128
#define H_   512
#define G3H  1536
#define BT   (B_ * T_)

// ---------------------------------------------------------------------------
// Scratch (static device allocations; harness forbids cudaMalloc)
// ---------------------------------------------------------------------------
__device__ float g_xg[(size_t)BT * G3H];   // 402 MB: input-gate projections
__device__ float g_y0[(size_t)BT * H_];    // 134 MB: layer0 outputs
__device__ float g_hT[B_ * H_];            // final hidden of layer 1
// h in A-fragment order, bf16 hi/lo, double buffered:
// [buf][hi=0/lo=1][ (m16*32 + ks)*32 + lane ] each uint4 = regs a0..a3 (2 bf16 each)
__device__ uint4 g_hfrag[2][2][16 * 32 * 32];
__device__ unsigned g_bar_cnt;
__device__ volatile unsigned g_bar_gen;

// ---------------------------------------------------------------------------
// Software grid barrier (128 blocks, all co-resident)
// ---------------------------------------------------------------------------
__device__ __forceinline__ void grid_barrier(unsigned nb) {
    __syncthreads();
    if (threadIdx.x == 0) {
        __threadfence();
        unsigned gen = g_bar_gen;
        if (atomicAdd(&g_bar_cnt, 1u) == nb - 1u) {
            atomicExch(&g_bar_cnt, 0u);
            __threadfence();
            g_bar_gen = gen + 1u;
        } else {
            while (g_bar_gen == gen) { __nanosleep(64); }
        }
        __threadfence();
    }
    __syncthreads();
}

// ---------------------------------------------------------------------------
// tf32 helpers (projection GEMM)
// ---------------------------------------------------------------------------
__device__ __forceinline__ uint32_t f2tf(float f) {
    uint32_t u;
    asm("cvt.rna.tf32.f32 %0, %1;" : "=r"(u) : "f"(f));
    return u;
}

__device__ __forceinline__ void mma_tf32(float* c, const uint32_t* a, const uint32_t* b) {
    asm volatile(
        "mma.sync.aligned.m16n8k8.row.col.f32.tf32.tf32.f32 "
        "{%0,%1,%2,%3}, {%4,%5,%6,%7}, {%8,%9}, {%0,%1,%2,%3};\n"
        : "+f"(c[0]), "+f"(c[1]), "+f"(c[2]), "+f"(c[3])
        : "r"(a[0]), "r"(a[1]), "r"(a[2]), "r"(a[3]), "r"(b[0]), "r"(b[1]));
}

// bf16 mma m16n8k16, fp32 accum
__device__ __forceinline__ void mma_bf16(float* c, const uint4& a, uint32_t b0, uint32_t b1) {
    asm volatile(
        "mma.sync.aligned.m16n8k16.row.col.f32.bf16.bf16.f32 "
        "{%0,%1,%2,%3}, {%4,%5,%6,%7}, {%8,%9}, {%0,%1,%2,%3};\n"
        : "+f"(c[0]), "+f"(c[1]), "+f"(c[2]), "+f"(c[3])
        : "r"(a.x), "r"(a.y), "r"(a.z), "r"(a.w), "r"(b0), "r"(b1));
}

__device__ __forceinline__ uint32_t pack_bf16(float lo_elem, float hi_elem) {
    __nv_bfloat162 t = __floats2bfloat162_rn(lo_elem, hi_elem);  // .x = low half
    return *(uint32_t*)&t;
}

// ---------------------------------------------------------------------------
// tf32 tensor-core GEMM: C[M, 1536] = A[M, K] @ W[1536, K]^T + bias  (unchanged)
// ---------------------------------------------------------------------------
__global__ void __launch_bounds__(256) gemm_tf32_kernel(
    const float* __restrict__ A, const float* __restrict__ W,
    const float* __restrict__ bias, int K, float* __restrict__ C)
{
    __shared__ uint32_t As[128][36];
    __shared__ uint32_t Bs[128][36];

    const int tid  = threadIdx.x;
    const int m0   = blockIdx.y * 128;
    const int n0   = blockIdx.x * 128;
    const int warp = tid >> 5, lane = tid & 31;
    const int wm = warp >> 2, wn = warp & 3;
    const int g  = lane >> 2, tg = lane & 3;

    float acc[4][4][4] = {};

    for (int k0 = 0; k0 < K; k0 += 32) {
#pragma unroll
        for (int r = 0; r < 4; r++) {
            int f   = tid + (r << 8);
            int row = f >> 3;
            int c4  = (f & 7) << 2;
            float4 va = *(const float4*)(A + (size_t)(m0 + row) * K + k0 + c4);
            As[row][c4 + 0] = f2tf(va.x);
            As[row][c4 + 1] = f2tf(va.y);
            As[row][c4 + 2] = f2tf(va.z);
            As[row][c4 + 3] = f2tf(va.w);
            float4 vb = *(const float4*)(W + (size_t)(n0 + row) * K + k0 + c4);
            Bs[row][c4 + 0] = f2tf(vb.x);
            Bs[row][c4 + 1] = f2tf(vb.y);
            Bs[row][c4 + 2] = f2tf(vb.z);
            Bs[row][c4 + 3] = f2tf(vb.w);
        }
        __syncthreads();

#pragma unroll
        for (int s = 0; s < 4; s++) {
            const int kb = s << 3;
            uint32_t a[4][4], b[4][2];
#pragma unroll
            for (int i = 0; i < 4; i++) {
                int r0 = wm * 64 + i * 16 + g;
                a[i][0] = As[r0][kb + tg];
                a[i][1] = As[r0 + 8][kb + tg];
                a[i][2] = As[r0][kb + tg + 4];
                a[i][3] = As[r0 + 8][kb + tg + 4];
            }
#pragma unroll
            for (int j = 0; j < 4; j++) {
                int c = wn * 32 + j * 8 + g;
                b[j][0] = Bs[c][kb + tg];
                b[j][1] = Bs[c][kb + tg + 4];
            }
#pragma unroll
            for (int i = 0; i < 4; i++)
#pragma unroll
                for (int j = 0; j < 4; j++)
                    mma_tf32(acc[i][j], a[i], b[j]);
        }
        __syncthreads();
    }

#pragma unroll
    for (int i = 0; i < 4; i++) {
        int r0 = m0 + wm * 64 + i * 16 + g;
#pragma unroll
        for (int j = 0; j < 4; j++) {
            int col = n0 + wn * 32 + j * 8 + tg * 2;
            float2 bv = *(const float2*)(bias + col);
            float2 o0 = make_float2(acc[i][j][0] + bv.x, acc[i][j][1] + bv.y);
            float2 o1 = make_float2(acc[i][j][2] + bv.x, acc[i][j][3] + bv.y);
            *(float2*)(C + (size_t)r0 * G3H + col)       = o0;
            *(float2*)(C + (size_t)(r0 + 8) * G3H + col) = o1;
        }
    }
}

// ---------------------------------------------------------------------------
// Tensor-core persistent GRU recurrence, bf16x3 (hi*hi + hi*lo + lo*hi).
// grid = 128 blocks x 256 threads. Block (mt, jt): batch rows [mt*64, +64),
// hidden cols [jt*16, +16). Per step: C[64 x 48] = h[64 x 512] @ Whh_tile^T.
// W fragments live in smem (built once); h fragments live in global in
// A-fragment order (written by the epilogue of the producing block).
// ---------------------------------------------------------------------------
#define CSTRIDE 50

template<bool WRITE_Y>
__global__ void __launch_bounds__(256, 1) gru_rec_kernel(
    const float* __restrict__ Whh, const float* __restrict__ bhh)
{
    extern __shared__ char smraw[];
    uint4* Wf   = (uint4*)smraw;                 // 6*32*32 uint4 = 96KB
    float* Csm  = (float*)(smraw + 6 * 32 * 32 * 16);  // 64 x CSTRIDE floats

    const int tid  = threadIdx.x;
    const int bid  = blockIdx.x;
    const int jt   = bid & 31, mt = bid >> 5;
    const int m0   = mt * 64, j0 = jt * 16;
    const int warp = tid >> 5, lane = tid & 31;
    const int wm   = warp >> 1, wn = warp & 1;   // 4 x 2 warp grid
    const int g    = lane >> 2, tg = lane & 3;
    const int m16  = mt * 4 + wm;
    const int ty   = tid >> 4, tx = tid & 15;    // epilogue mapping
    const int ty4  = ty << 2;
    const int j    = j0 + tx;

    // ---- Build W fragments in smem (once). n = gate*16 + jj (0..47) ----
    for (int idx = tid; idx < 48 * 256; idx += 256) {
        int n  = idx >> 8;           // 0..47
        int kp = idx & 255;          // k-pair index
        int k  = kp << 1;
        int gate = n >> 4, jj = n & 15;
        const float* wrow = Whh + ((size_t)(gate * H_ + j0 + jj)) * H_;
        float w0 = wrow[k], w1 = wrow[k + 1];
        float h0 = __bfloat162float(__float2bfloat16(w0));
        float h1 = __bfloat162float(__float2bfloat16(w1));
        uint32_t hi = pack_bf16(h0, h1);
        uint32_t lo = pack_bf16(w0 - h0, w1 - h1);
        int nt = n >> 3, gq = n & 7;
        int ks = k >> 4, kr = k & 15;
        int rr   = (kr >= 8) ? 1 : 0;
        int tigw = (kr >> 1) & 3;
        int lw   = gq * 4 + tigw;
        uint32_t* Wu = (uint32_t*)Wf;
        int base = (((nt * 32 + ks) * 32 + lw) << 2);
        Wu[base + rr]     = hi;   // q0/q1 = b0_hi/b1_hi
        Wu[base + 2 + rr] = lo;   // q2/q3 = b0_lo/b1_lo
    }

    // ---- Zero h fragment buffer 0 (hi and lo) ----
    {
        int idx = bid * 256 + tid;          // 0..32767
        uint4 z = make_uint4(0, 0, 0, 0);
        if (idx < 16384) g_hfrag[0][0][idx] = z;
        else             g_hfrag[0][1][idx - 16384] = z;
    }

    // biases for this thread's hidden column
    const float bb0 = bhh[0 * H_ + j];
    const float bb1 = bhh[1 * H_ + j];
    const float bb2 = bhh[2 * H_ + j];

    float hreg[4] = {0.f, 0.f, 0.f, 0.f};   // h_old for this thread's 4 outputs

    grid_barrier(128);

    for (int t = 0; t < T_; t++) {
        // ---- prefetch xg for this thread's 4 outputs (hides DRAM latency) ----
        float xr[4], xz[4], xn[4];
#pragma unroll
        for (int i = 0; i < 4; i++) {
            int m = m0 + ty4 + i;
            size_t xb = ((size_t)m * T_ + t) * G3H + j;
            xr[i] = g_xg[xb];
            xz[i] = g_xg[xb + H_];
            xn[i] = g_xg[xb + 2 * H_];
        }

        const uint4* __restrict__ Ahi = g_hfrag[t & 1][0];
        const uint4* __restrict__ Alo = g_hfrag[t & 1][1];

        float C[3][4] = {};

#pragma unroll 4
        for (int ks = 0; ks < 32; ks++) {
            size_t fidx = ((size_t)(m16 * 32 + ks)) * 32 + lane;
            uint4 ahi = Ahi[fidx];
            uint4 alo = Alo[fidx];
#pragma unroll
            for (int nt = 0; nt < 3; nt++) {
                uint4 w = Wf[((wn * 3 + nt) * 32 + ks) * 32 + lane];
                mma_bf16(C[nt], ahi, w.x, w.y);   // hi*hi
                mma_bf16(C[nt], ahi, w.z, w.w);   // hi*lo
                mma_bf16(C[nt], alo, w.x, w.y);   // lo*hi
            }
        }

        // ---- stage C to smem for gate math (frag -> (m, gate*16+jj)) ----
#pragma unroll
        for (int nt = 0; nt < 3; nt++) {
            int cbase = (wn * 3 + nt) * 8 + 2 * tg;
            int r0 = wm * 16 + g;
            *(float2*)&Csm[r0 * CSTRIDE + cbase]       = make_float2(C[nt][0], C[nt][1]);
            *(float2*)&Csm[(r0 + 8) * CSTRIDE + cbase] = make_float2(C[nt][2], C[nt][3]);
        }
        __syncthreads();

        // ---- gate update: 4 outputs per thread ----
        const int nb = (t + 1) & 1;
        __nv_bfloat16* Hhi = (__nv_bfloat16*)g_hfrag[nb][0];
        __nv_bfloat16* Hlo = (__nv_bfloat16*)g_hfrag[nb][1];

#pragma unroll
        for (int i = 0; i < 4; i++) {
            int ml = ty4 + i;
            float cr = Csm[ml * CSTRIDE + tx];
            float cz = Csm[ml * CSTRIDE + 16 + tx];
            float cn = Csm[ml * CSTRIDE + 32 + tx];

            float r = 1.0f / (1.0f + expf(-(xr[i] + cr + bb0)));
            float z = 1.0f / (1.0f + expf(-(xz[i] + cz + bb1)));
            float n = tanhf(xn[i] + r * (cn + bb2));

            float hnew = (1.0f - z) * n + z * hreg[i];
            hreg[i] = hnew;

            // write h as bf16 hi/lo into A-fragment order
            float fh = __bfloat162float(__float2bfloat16(hnew));
            int gm   = ml & 15;
            int rr   = ((tx >= 8) ? 2 : 0) + ((gm >= 8) ? 1 : 0);
            int tigp = (tx >> 1) & 3;
            int lp   = (gm & 7) * 4 + tigp;
            int half = tx & 1;
            size_t bidx = (((size_t)((mt * 4 + (ml >> 4)) * 32 + jt)) * 32 + lp) * 8 + rr * 2 + half;
            Hhi[bidx] = __float2bfloat16(fh);
            Hlo[bidx] = __float2bfloat16(hnew - fh);

            int m = m0 + ml;
            if (WRITE_Y) {
                g_y0[((size_t)m * T_ + t) * H_ + j] = hnew;
            } else if (t == T_ - 1) {
                g_hT[(size_t)m * H_ + j] = hnew;
            }
        }

        grid_barrier(128);
    }
}

// ---------------------------------------------------------------------------
// Head: out = relu(relu(hT) @ fc1^T + b1) @ fc2^T + b2
// ---------------------------------------------------------------------------
__global__ void __launch_bounds__(128) head_kernel(
    const float* __restrict__ w1, const float* __restrict__ b1,
    const float* __restrict__ w2, const float* __restrict__ b2,
    float* __restrict__ out)
{
    __shared__ float sh[H_];
    __shared__ float s1[128];
    const int b = blockIdx.x;
    const int tid = threadIdx.x;

#pragma unroll
    for (int r = 0; r < 4; r++) {
        float v = g_hT[(size_t)b * H_ + tid + r * 128];
        sh[tid + r * 128] = fmaxf(v, 0.0f);
    }
    __syncthreads();

    float acc = b1[tid];
    const float* wrow = w1 + (size_t)tid * H_;
#pragma unroll 8
    for (int jj = 0; jj < H_; jj++) acc = fmaf(sh[jj], __ldg(wrow + jj), acc);
    s1[tid] = fmaxf(acc, 0.0f);
    __syncthreads();

    if (tid < 10) {
        float a = b2[tid];
        const float* w2row = w2 + (size_t)tid * 128;
#pragma unroll 8
        for (int i = 0; i < 128; i++) a = fmaf(s1[i], __ldg(w2row + i), a);
        out[(size_t)b * 10 + tid] = a;
    }
}

// ---------------------------------------------------------------------------
// Launch
// ---------------------------------------------------------------------------
extern "C" void kernel_launch(void* const* d_in, const int* in_sizes, int n_in,
                              void* d_out, int out_size)
{
    const float* x    = (const float*)d_in[0];
    const float* Wih0 = (const float*)d_in[1];
    const float* Whh0 = (const float*)d_in[2];
    const float* bih0 = (const float*)d_in[3];
    const float* bhh0 = (const float*)d_in[4];
    const float* Wih1 = (const float*)d_in[5];
    const float* Whh1 = (const float*)d_in[6];
    const float* bih1 = (const float*)d_in[7];
    const float* bhh1 = (const float*)d_in[8];
    const float* fc1w = (const float*)d_in[9];
    const float* fc1b = (const float*)d_in[10];
    const float* fc2w = (const float*)d_in[11];
    const float* fc2b = (const float*)d_in[12];
    float* out = (float*)d_out;

    float* y0_ptr = nullptr;
    float* xg_ptr = nullptr;
    cudaGetSymbolAddress((void**)&y0_ptr, g_y0);
    cudaGetSymbolAddress((void**)&xg_ptr, g_xg);

    const int rec_smem = 6 * 32 * 32 * 16 + 64 * CSTRIDE * 4;   // 96KB + 12.5KB
    cudaFuncSetAttribute((const void*)gru_rec_kernel<true>,
                         cudaFuncAttributeMaxDynamicSharedMemorySize, rec_smem);
    cudaFuncSetAttribute((const void*)gru_rec_kernel<false>,
                         cudaFuncAttributeMaxDynamicSharedMemorySize, rec_smem);

    dim3 gemm_grid(G3H / 128, BT / 128);  // (12, 512)

    // Phase 1: xg0 = x @ W_ih0^T + b_ih0   (K = 128)
    gemm_tf32_kernel<<<gemm_grid, 256>>>(x, Wih0, bih0, D_, xg_ptr);

    // Phase 2: layer-0 recurrence (tensor cores), writes y0
    gru_rec_kernel<true><<<128, 256, rec_smem>>>(Whh0, bhh0);

    // Phase 3: xg1 = y0 @ W_ih1^T + b_ih1  (K = 512)
    gemm_tf32_kernel<<<gemm_grid, 256>>>(y0_ptr, Wih1, bih1, H_, xg_ptr);

    // Phase 4: layer-1 recurrence
    gru_rec_kernel<false><<<128, 256, rec_smem>>>(Whh1, bhh1);

    // Phase 5: MLP head
    head_kernel<<<B_, 128>>>(fc1w, fc1b, fc2w, fc2b, out);
}

// round 4
// speedup vs baseline: 3.0471x; 1.0406x over previous
#include <cuda_runtime.h>
#include <cuda_bf16.h>
#include <math.h>
#include <stdint.h>

// Problem dims (fixed by the dataset)
#define B_   256
#define T_   256
#define D_   128
#define H_   512
#define G3H  1536
#define BT   (B_ * T_)

// ---------------------------------------------------------------------------
// Scratch (static device allocations; harness forbids cudaMalloc)
// ---------------------------------------------------------------------------
__device__ float g_xg[(size_t)BT * G3H];   // 402 MB: input-gate projections
__device__ float g_y0[(size_t)BT * H_];    // 134 MB: layer0 outputs
__device__ float g_hT[B_ * H_];            // final hidden of layer 1
// h in A-fragment order, bf16 hi/lo, double buffered:
// [buf][hi=0/lo=1][ (m16*32 + ks)*32 + lane ], each uint4 = regs a0..a3
__device__ uint4 g_hfrag[2][2][16 * 32 * 32];

// per-mt-group barrier slots, 128B padded
struct BarSlot { unsigned cnt; volatile unsigned gen; unsigned pad[30]; };
__device__ BarSlot g_bar[4];

// ---------------------------------------------------------------------------
// Group barrier: 32 blocks sharing one mt group
// ---------------------------------------------------------------------------
__device__ __forceinline__ void group_barrier(int grp) {
    __syncthreads();
    if (threadIdx.x == 0) {
        __threadfence();
        unsigned gen = g_bar[grp].gen;      // read BEFORE arriving
        if (atomicAdd(&g_bar[grp].cnt, 1u) == 31u) {
            atomicExch(&g_bar[grp].cnt, 0u);
            __threadfence();
            g_bar[grp].gen = gen + 1u;
        } else {
            while (g_bar[grp].gen == gen) { __nanosleep(32); }
        }
        __threadfence();
    }
    __syncthreads();
}

// ---------------------------------------------------------------------------
// tf32 helpers (projection GEMM)
// ---------------------------------------------------------------------------
__device__ __forceinline__ uint32_t f2tf(float f) {
    uint32_t u;
    asm("cvt.rna.tf32.f32 %0, %1;" : "=r"(u) : "f"(f));
    return u;
}

__device__ __forceinline__ void mma_tf32(float* c, const uint32_t* a, const uint32_t* b) {
    asm volatile(
        "mma.sync.aligned.m16n8k8.row.col.f32.tf32.tf32.f32 "
        "{%0,%1,%2,%3}, {%4,%5,%6,%7}, {%8,%9}, {%0,%1,%2,%3};\n"
        : "+f"(c[0]), "+f"(c[1]), "+f"(c[2]), "+f"(c[3])
        : "r"(a[0]), "r"(a[1]), "r"(a[2]), "r"(a[3]), "r"(b[0]), "r"(b[1]));
}

// bf16 mma m16n8k16, fp32 accum
__device__ __forceinline__ void mma_bf16(float* c, const uint4& a, uint32_t b0, uint32_t b1) {
    asm volatile(
        "mma.sync.aligned.m16n8k16.row.col.f32.bf16.bf16.f32 "
        "{%0,%1,%2,%3}, {%4,%5,%6,%7}, {%8,%9}, {%0,%1,%2,%3};\n"
        : "+f"(c[0]), "+f"(c[1]), "+f"(c[2]), "+f"(c[3])
        : "r"(a.x), "r"(a.y), "r"(a.z), "r"(a.w), "r"(b0), "r"(b1));
}

__device__ __forceinline__ uint32_t pack2_bf16(float e0, float e1) {
    __nv_bfloat162 t = __floats2bfloat162_rn(e0, e1);  // .x = low half
    return *(uint32_t*)&t;
}

// ---------------------------------------------------------------------------
// tf32 tensor-core GEMM: C[M, 1536] = A[M, K] @ W[1536, K]^T + bias
// ---------------------------------------------------------------------------
__global__ void __launch_bounds__(256) gemm_tf32_kernel(
    const float* __restrict__ A, const float* __restrict__ W,
    const float* __restrict__ bias, int K, float* __restrict__ C)
{
    __shared__ uint32_t As[128][36];
    __shared__ uint32_t Bs[128][36];

    const int tid  = threadIdx.x;
    const int m0   = blockIdx.y * 128;
    const int n0   = blockIdx.x * 128;
    const int warp = tid >> 5, lane = tid & 31;
    const int wm = warp >> 2, wn = warp & 3;
    const int g  = lane >> 2, tg = lane & 3;

    float acc[4][4][4] = {};

    for (int k0 = 0; k0 < K; k0 += 32) {
#pragma unroll
        for (int r = 0; r < 4; r++) {
            int f   = tid + (r << 8);
            int row = f >> 3;
            int c4  = (f & 7) << 2;
            float4 va = *(const float4*)(A + (size_t)(m0 + row) * K + k0 + c4);
            As[row][c4 + 0] = f2tf(va.x);
            As[row][c4 + 1] = f2tf(va.y);
            As[row][c4 + 2] = f2tf(va.z);
            As[row][c4 + 3] = f2tf(va.w);
            float4 vb = *(const float4*)(W + (size_t)(n0 + row) * K + k0 + c4);
            Bs[row][c4 + 0] = f2tf(vb.x);
            Bs[row][c4 + 1] = f2tf(vb.y);
            Bs[row][c4 + 2] = f2tf(vb.z);
            Bs[row][c4 + 3] = f2tf(vb.w);
        }
        __syncthreads();

#pragma unroll
        for (int s = 0; s < 4; s++) {
            const int kb = s << 3;
            uint32_t a[4][4], b[4][2];
#pragma unroll
            for (int i = 0; i < 4; i++) {
                int r0 = wm * 64 + i * 16 + g;
                a[i][0] = As[r0][kb + tg];
                a[i][1] = As[r0 + 8][kb + tg];
                a[i][2] = As[r0][kb + tg + 4];
                a[i][3] = As[r0 + 8][kb + tg + 4];
            }
#pragma unroll
            for (int j = 0; j < 4; j++) {
                int c = wn * 32 + j * 8 + g;
                b[j][0] = Bs[c][kb + tg];
                b[j][1] = Bs[c][kb + tg + 4];
            }
#pragma unroll
            for (int i = 0; i < 4; i++)
#pragma unroll
                for (int j = 0; j < 4; j++)
                    mma_tf32(acc[i][j], a[i], b[j]);
        }
        __syncthreads();
    }

#pragma unroll
    for (int i = 0; i < 4; i++) {
        int r0 = m0 + wm * 64 + i * 16 + g;
#pragma unroll
        for (int j = 0; j < 4; j++) {
            int col = n0 + wn * 32 + j * 8 + tg * 2;
            float2 bv = *(const float2*)(bias + col);
            float2 o0 = make_float2(acc[i][j][0] + bv.x, acc[i][j][1] + bv.y);
            float2 o1 = make_float2(acc[i][j][2] + bv.x, acc[i][j][3] + bv.y);
            *(float2*)(C + (size_t)r0 * G3H + col)       = o0;
            *(float2*)(C + (size_t)(r0 + 8) * G3H + col) = o1;
        }
    }
}

// ---------------------------------------------------------------------------
// Tensor-core persistent GRU recurrence, bf16x3 (hi*hi + hi*lo + lo*hi).
// grid = 128 blocks x 256 threads. Block (mt, jt): batch rows [mt*64, +64),
// hidden cols [jt*16, +16). Barrier only among the 32 blocks of one mt group.
// h-fragment stores are staged through smem and written as coalesced uint4.
// ---------------------------------------------------------------------------
#define CSTRIDE 50
#define HSTRIDE 17

template<bool WRITE_Y>
__global__ void __launch_bounds__(256, 1) gru_rec_kernel(
    const float* __restrict__ Whh, const float* __restrict__ bhh)
{
    extern __shared__ char smraw[];
    uint4* Wf   = (uint4*)smraw;                              // 6*32*32 uint4 = 96KB
    float* Csm  = (float*)(smraw + 6 * 32 * 32 * 16);         // 64 x CSTRIDE
    float* Hsm  = Csm + 64 * CSTRIDE;                         // 64 x HSTRIDE

    const int tid  = threadIdx.x;
    const int bid  = blockIdx.x;
    const int jt   = bid & 31, mt = bid >> 5;
    const int m0   = mt * 64, j0 = jt * 16;
    const int warp = tid >> 5, lane = tid & 31;
    const int wm   = warp >> 1, wn = warp & 1;   // 4 x 2 warp grid
    const int g    = lane >> 2, tg = lane & 3;
    const int m16  = mt * 4 + wm;
    const int ty   = tid >> 4, tx = tid & 15;    // epilogue mapping
    const int ty4  = ty << 2;
    const int j    = j0 + tx;

    // ---- Build W fragments in smem (once). n = gate*16 + jj (0..47) ----
    for (int idx = tid; idx < 48 * 256; idx += 256) {
        int n  = idx >> 8;
        int kp = idx & 255;
        int k  = kp << 1;
        int gate = n >> 4, jj = n & 15;
        const float* wrow = Whh + ((size_t)(gate * H_ + j0 + jj)) * H_;
        float w0 = wrow[k], w1 = wrow[k + 1];
        float h0 = __bfloat162float(__float2bfloat16(w0));
        float h1 = __bfloat162float(__float2bfloat16(w1));
        uint32_t hi = pack2_bf16(h0, h1);
        uint32_t lo = pack2_bf16(w0 - h0, w1 - h1);
        int nt = n >> 3, gq = n & 7;
        int ks = k >> 4, kr = k & 15;
        int rr   = (kr >= 8) ? 1 : 0;
        int tigw = (kr >> 1) & 3;
        int lw   = gq * 4 + tigw;
        uint32_t* Wu = (uint32_t*)Wf;
        int base = (((nt * 32 + ks) * 32 + lw) << 2);
        Wu[base + rr]     = hi;
        Wu[base + 2 + rr] = lo;
    }

    // ---- Zero h fragment buffer 0 for THIS group only ----
    {
        int idx = (bid & 31) * 256 + tid;        // 0..8191 within group
        size_t base = (size_t)mt * 4096;
        uint4 z = make_uint4(0, 0, 0, 0);
        if (idx < 4096) g_hfrag[0][0][base + idx] = z;
        else            g_hfrag[0][1][base + idx - 4096] = z;
    }

    const float bb0 = bhh[0 * H_ + j];
    const float bb1 = bhh[1 * H_ + j];
    const float bb2 = bhh[2 * H_ + j];

    float hreg[4] = {0.f, 0.f, 0.f, 0.f};

    group_barrier(mt);

    for (int t = 0; t < T_; t++) {
        // ---- prefetch xg for this thread's 4 outputs ----
        float xr[4], xz[4], xn[4];
#pragma unroll
        for (int i = 0; i < 4; i++) {
            int m = m0 + ty4 + i;
            size_t xb = ((size_t)m * T_ + t) * G3H + j;
            xr[i] = g_xg[xb];
            xz[i] = g_xg[xb + H_];
            xn[i] = g_xg[xb + 2 * H_];
        }

        const uint4* __restrict__ Ahi = g_hfrag[t & 1][0];
        const uint4* __restrict__ Alo = g_hfrag[t & 1][1];

        float C[3][4] = {};

#pragma unroll 4
        for (int ks = 0; ks < 32; ks++) {
            size_t fidx = ((size_t)(m16 * 32 + ks)) * 32 + lane;
            uint4 ahi = Ahi[fidx];
            uint4 alo = Alo[fidx];
#pragma unroll
            for (int nt = 0; nt < 3; nt++) {
                uint4 w = Wf[((wn * 3 + nt) * 32 + ks) * 32 + lane];
                mma_bf16(C[nt], ahi, w.x, w.y);   // hi*hi
                mma_bf16(C[nt], ahi, w.z, w.w);   // hi*lo
                mma_bf16(C[nt], alo, w.x, w.y);   // lo*hi
            }
        }

        // ---- stage C to smem for gate math ----
#pragma unroll
        for (int nt = 0; nt < 3; nt++) {
            int cbase = (wn * 3 + nt) * 8 + 2 * tg;
            int r0 = wm * 16 + g;
            *(float2*)&Csm[r0 * CSTRIDE + cbase]       = make_float2(C[nt][0], C[nt][1]);
            *(float2*)&Csm[(r0 + 8) * CSTRIDE + cbase] = make_float2(C[nt][2], C[nt][3]);
        }
        __syncthreads();

        // ---- gate update: 4 outputs per thread; stage hnew in smem ----
#pragma unroll
        for (int i = 0; i < 4; i++) {
            int ml = ty4 + i;
            float cr = Csm[ml * CSTRIDE + tx];
            float cz = Csm[ml * CSTRIDE + 16 + tx];
            float cn = Csm[ml * CSTRIDE + 32 + tx];

            float r = 1.0f / (1.0f + expf(-(xr[i] + cr + bb0)));
            float z = 1.0f / (1.0f + expf(-(xz[i] + cz + bb1)));
            float n = tanhf(xn[i] + r * (cn + bb2));

            float hnew = (1.0f - z) * n + z * hreg[i];
            hreg[i] = hnew;
            Hsm[ml * HSTRIDE + tx] = hnew;

            int m = m0 + ml;
            if (WRITE_Y) {
                g_y0[((size_t)m * T_ + t) * H_ + j] = hnew;
            } else if (t == T_ - 1) {
                g_hT[(size_t)m * H_ + j] = hnew;
            }
        }
        __syncthreads();

        // ---- pack h fragments: 128 threads, each 1 fragment (uint4 hi + lo) ----
        if (tid < 128) {
            const int m16l = tid >> 5;
            const int ln   = tid & 31;
            const int gg   = ln >> 2, tg2 = ln & 3;
            const int r0 = m16l * 16 + gg, r1 = r0 + 8;
            const int k0 = tg2 * 2;

            float v[8];
            v[0] = Hsm[r0 * HSTRIDE + k0];     v[1] = Hsm[r0 * HSTRIDE + k0 + 1];
            v[2] = Hsm[r1 * HSTRIDE + k0];     v[3] = Hsm[r1 * HSTRIDE + k0 + 1];
            v[4] = Hsm[r0 * HSTRIDE + k0 + 8]; v[5] = Hsm[r0 * HSTRIDE + k0 + 9];
            v[6] = Hsm[r1 * HSTRIDE + k0 + 8]; v[7] = Hsm[r1 * HSTRIDE + k0 + 9];

            float fh[8], fl[8];
#pragma unroll
            for (int q = 0; q < 8; q++) {
                fh[q] = __bfloat162float(__float2bfloat16(v[q]));
                fl[q] = v[q] - fh[q];
            }
            uint4 hi, lo;
            hi.x = pack2_bf16(fh[0], fh[1]); hi.y = pack2_bf16(fh[2], fh[3]);
            hi.z = pack2_bf16(fh[4], fh[5]); hi.w = pack2_bf16(fh[6], fh[7]);
            lo.x = pack2_bf16(fl[0], fl[1]); lo.y = pack2_bf16(fl[2], fl[3]);
            lo.z = pack2_bf16(fl[4], fl[5]); lo.w = pack2_bf16(fl[6], fl[7]);

            const int nb = (t + 1) & 1;
            size_t base = ((size_t)((mt * 4 + m16l) * 32 + jt)) * 32 + ln;
            g_hfrag[nb][0][base] = hi;
            g_hfrag[nb][1][base] = lo;
        }

        group_barrier(mt);
    }
}

// ---------------------------------------------------------------------------
// Head: out = relu(relu(hT) @ fc1^T + b1) @ fc2^T + b2
// ---------------------------------------------------------------------------
__global__ void __launch_bounds__(128) head_kernel(
    const float* __restrict__ w1, const float* __restrict__ b1,
    const float* __restrict__ w2, const float* __restrict__ b2,
    float* __restrict__ out)
{
    __shared__ float sh[H_];
    __shared__ float s1[128];
    const int b = blockIdx.x;
    const int tid = threadIdx.x;

#pragma unroll
    for (int r = 0; r < 4; r++) {
        float v = g_hT[(size_t)b * H_ + tid + r * 128];
        sh[tid + r * 128] = fmaxf(v, 0.0f);
    }
    __syncthreads();

    float acc = b1[tid];
    const float* wrow = w1 + (size_t)tid * H_;
#pragma unroll 8
    for (int jj = 0; jj < H_; jj++) acc = fmaf(sh[jj], __ldg(wrow + jj), acc);
    s1[tid] = fmaxf(acc, 0.0f);
    __syncthreads();

    if (tid < 10) {
        float a = b2[tid];
        const float* w2row = w2 + (size_t)tid * 128;
#pragma unroll 8
        for (int i = 0; i < 128; i++) a = fmaf(s1[i], __ldg(w2row + i), a);
        out[(size_t)b * 10 + tid] = a;
    }
}

// ---------------------------------------------------------------------------
// Launch
// ---------------------------------------------------------------------------
extern "C" void kernel_launch(void* const* d_in, const int* in_sizes, int n_in,
                              void* d_out, int out_size)
{
    const float* x    = (const float*)d_in[0];
    const float* Wih0 = (const float*)d_in[1];
    const float* Whh0 = (const float*)d_in[2];
    const float* bih0 = (const float*)d_in[3];
    const float* bhh0 = (const float*)d_in[4];
    const float* Wih1 = (const float*)d_in[5];
    const float* Whh1 = (const float*)d_in[6];
    const float* bih1 = (const float*)d_in[7];
    const float* bhh1 = (const float*)d_in[8];
    const float* fc1w = (const float*)d_in[9];
    const float* fc1b = (const float*)d_in[10];
    const float* fc2w = (const float*)d_in[11];
    const float* fc2b = (const float*)d_in[12];
    float* out = (float*)d_out;

    float* y0_ptr = nullptr;
    float* xg_ptr = nullptr;
    cudaGetSymbolAddress((void**)&y0_ptr, g_y0);
    cudaGetSymbolAddress((void**)&xg_ptr, g_xg);

    const int rec_smem = 6 * 32 * 32 * 16 + (64 * CSTRIDE + 64 * HSTRIDE) * 4;
    cudaFuncSetAttribute((const void*)gru_rec_kernel<true>,
                         cudaFuncAttributeMaxDynamicSharedMemorySize, rec_smem);
    cudaFuncSetAttribute((const void*)gru_rec_kernel<false>,
                         cudaFuncAttributeMaxDynamicSharedMemorySize, rec_smem);

    dim3 gemm_grid(G3H / 128, BT / 128);  // (12, 512)

    // Phase 1: xg0 = x @ W_ih0^T + b_ih0   (K = 128)
    gemm_tf32_kernel<<<gemm_grid, 256>>>(x, Wih0, bih0, D_, xg_ptr);

    // Phase 2: layer-0 recurrence (tensor cores), writes y0
    gru_rec_kernel<true><<<128, 256, rec_smem>>>(Whh0, bhh0);

    // Phase 3: xg1 = y0 @ W_ih1^T + b_ih1  (K = 512)
    gemm_tf32_kernel<<<gemm_grid, 256>>>(y0_ptr, Wih1, bih1, H_, xg_ptr);

    // Phase 4: layer-1 recurrence
    gru_rec_kernel<false><<<128, 256, rec_smem>>>(Whh1, bhh1);

    // Phase 5: MLP head
    head_kernel<<<B_, 128>>>(fc1w, fc1b, fc2w, fc2b, out);
}

// round 5
// speedup vs baseline: 3.2057x; 1.0521x over previous
#include <cuda_runtime.h>
#include <cuda_bf16.h>
#include <math.h>
#include <stdint.h>

// Problem dims (fixed by the dataset)
#define B_   256
#define T_   256
#define D_   128
#define H_   512
#define G3H  1536
#define BT   (B_ * T_)

// ---------------------------------------------------------------------------
// Scratch (static device allocations; harness forbids cudaMalloc)
// ---------------------------------------------------------------------------
__device__ float g_xg[(size_t)BT * G3H];   // 402 MB: xg0, overwritten in-place by xg1
__device__ float g_hT[B_ * H_];            // final hidden of layer 1
// h in A-fragment order, bf16 hi/lo, double buffered:
// [buf][hi=0/lo=1][ (m16*32 + ks)*32 + lane ], each uint4 = regs a0..a3
__device__ uint4 g_hfrag[2][2][16 * 32 * 32];

// per-mt-group barrier slots, 128B padded
struct BarSlot { unsigned cnt; volatile unsigned gen; unsigned pad[30]; };
__device__ BarSlot g_bar[4];

// ---------------------------------------------------------------------------
// Group barrier: 32 blocks sharing one mt group. Tight spin (no nanosleep).
// ---------------------------------------------------------------------------
__device__ __forceinline__ void group_barrier(int grp) {
    __syncthreads();
    if (threadIdx.x == 0) {
        __threadfence();
        unsigned gen = g_bar[grp].gen;      // read BEFORE arriving
        if (atomicAdd(&g_bar[grp].cnt, 1u) == 31u) {
            atomicExch(&g_bar[grp].cnt, 0u);
            __threadfence();
            g_bar[grp].gen = gen + 1u;
        } else {
            while (g_bar[grp].gen == gen) { }
        }
        __threadfence();
    }
    __syncthreads();
}

// ---------------------------------------------------------------------------
// tf32 helpers (projection GEMM)
// ---------------------------------------------------------------------------
__device__ __forceinline__ uint32_t f2tf(float f) {
    uint32_t u;
    asm("cvt.rna.tf32.f32 %0, %1;" : "=r"(u) : "f"(f));
    return u;
}

__device__ __forceinline__ void mma_tf32(float* c, const uint32_t* a, const uint32_t* b) {
    asm volatile(
        "mma.sync.aligned.m16n8k8.row.col.f32.tf32.tf32.f32 "
        "{%0,%1,%2,%3}, {%4,%5,%6,%7}, {%8,%9}, {%0,%1,%2,%3};\n"
        : "+f"(c[0]), "+f"(c[1]), "+f"(c[2]), "+f"(c[3])
        : "r"(a[0]), "r"(a[1]), "r"(a[2]), "r"(a[3]), "r"(b[0]), "r"(b[1]));
}

// bf16 mma m16n8k16, fp32 accum
__device__ __forceinline__ void mma_bf16(float* c, const uint4& a, uint32_t b0, uint32_t b1) {
    asm volatile(
        "mma.sync.aligned.m16n8k16.row.col.f32.bf16.bf16.f32 "
        "{%0,%1,%2,%3}, {%4,%5,%6,%7}, {%8,%9}, {%0,%1,%2,%3};\n"
        : "+f"(c[0]), "+f"(c[1]), "+f"(c[2]), "+f"(c[3])
        : "r"(a.x), "r"(a.y), "r"(a.z), "r"(a.w), "r"(b0), "r"(b1));
}

__device__ __forceinline__ uint32_t pack2_bf16(float e0, float e1) {
    __nv_bfloat162 t = __floats2bfloat162_rn(e0, e1);  // .x = low half
    return *(uint32_t*)&t;
}

// Build bf16 hi/lo B-fragments for a 48-col (3 gates x 16) x 512-k weight tile.
// slot_off selects where the 6 n-tiles land in the fragment array.
__device__ __forceinline__ void build_wfrag(
    uint32_t* Wu, const float* __restrict__ Wsrc, int j0, int tid, int slot_off)
{
    for (int idx = tid; idx < 48 * 256; idx += 256) {
        int n  = idx >> 8;
        int k  = (idx & 255) << 1;
        int gate = n >> 4, jj = n & 15;
        const float* wrow = Wsrc + ((size_t)(gate * H_ + j0 + jj)) * H_;
        float w0 = wrow[k], w1 = wrow[k + 1];
        float h0 = __bfloat162float(__float2bfloat16(w0));
        float h1 = __bfloat162float(__float2bfloat16(w1));
        uint32_t hi = pack2_bf16(h0, h1);
        uint32_t lo = pack2_bf16(w0 - h0, w1 - h1);
        int nt = (n >> 3) + slot_off;
        int ks = k >> 4, kr = k & 15;
        int rr   = (kr >= 8) ? 1 : 0;
        int lw   = (n & 7) * 4 + ((kr >> 1) & 3);
        int base = (((nt * 32 + ks) * 32 + lw) << 2);
        Wu[base + rr]     = hi;
        Wu[base + 2 + rr] = lo;
    }
}

// ---------------------------------------------------------------------------
// tf32 tensor-core GEMM: C[M, 1536] = A[M, K] @ W[1536, K]^T + bias (phase 1)
// ---------------------------------------------------------------------------
__global__ void __launch_bounds__(256) gemm_tf32_kernel(
    const float* __restrict__ A, const float* __restrict__ W,
    const float* __restrict__ bias, int K, float* __restrict__ C)
{
    __shared__ uint32_t As[128][36];
    __shared__ uint32_t Bs[128][36];

    const int tid  = threadIdx.x;
    const int m0   = blockIdx.y * 128;
    const int n0   = blockIdx.x * 128;
    const int warp = tid >> 5, lane = tid & 31;
    const int wm = warp >> 2, wn = warp & 3;
    const int g  = lane >> 2, tg = lane & 3;

    float acc[4][4][4] = {};

    for (int k0 = 0; k0 < K; k0 += 32) {
#pragma unroll
        for (int r = 0; r < 4; r++) {
            int f   = tid + (r << 8);
            int row = f >> 3;
            int c4  = (f & 7) << 2;
            float4 va = *(const float4*)(A + (size_t)(m0 + row) * K + k0 + c4);
            As[row][c4 + 0] = f2tf(va.x);
            As[row][c4 + 1] = f2tf(va.y);
            As[row][c4 + 2] = f2tf(va.z);
            As[row][c4 + 3] = f2tf(va.w);
            float4 vb = *(const float4*)(W + (size_t)(n0 + row) * K + k0 + c4);
            Bs[row][c4 + 0] = f2tf(vb.x);
            Bs[row][c4 + 1] = f2tf(vb.y);
            Bs[row][c4 + 2] = f2tf(vb.z);
            Bs[row][c4 + 3] = f2tf(vb.w);
        }
        __syncthreads();

#pragma unroll
        for (int s = 0; s < 4; s++) {
            const int kb = s << 3;
            uint32_t a[4][4], b[4][2];
#pragma unroll
            for (int i = 0; i < 4; i++) {
                int r0 = wm * 64 + i * 16 + g;
                a[i][0] = As[r0][kb + tg];
                a[i][1] = As[r0 + 8][kb + tg];
                a[i][2] = As[r0][kb + tg + 4];
                a[i][3] = As[r0 + 8][kb + tg + 4];
            }
#pragma unroll
            for (int jx = 0; jx < 4; jx++) {
                int c = wn * 32 + jx * 8 + g;
                b[jx][0] = Bs[c][kb + tg];
                b[jx][1] = Bs[c][kb + tg + 4];
            }
#pragma unroll
            for (int i = 0; i < 4; i++)
#pragma unroll
                for (int jx = 0; jx < 4; jx++)
                    mma_tf32(acc[i][jx], a[i], b[jx]);
        }
        __syncthreads();
    }

#pragma unroll
    for (int i = 0; i < 4; i++) {
        int r0 = m0 + wm * 64 + i * 16 + g;
#pragma unroll
        for (int jx = 0; jx < 4; jx++) {
            int col = n0 + wn * 32 + jx * 8 + tg * 2;
            float2 bv = *(const float2*)(bias + col);
            float2 o0 = make_float2(acc[i][jx][0] + bv.x, acc[i][jx][1] + bv.y);
            float2 o1 = make_float2(acc[i][jx][2] + bv.x, acc[i][jx][3] + bv.y);
            *(float2*)(C + (size_t)r0 * G3H + col)       = o0;
            *(float2*)(C + (size_t)(r0 + 8) * G3H + col) = o1;
        }
    }
}

#define CSTRIDE 50
#define HSTRIDE 17

// ---------------------------------------------------------------------------
// FUSED layer-0 recurrence + layer-1 input projection.
// grid = 128 blocks x 256 threads, block (mt, jt). Per step t:
//   C  = h(t-1) @ Whh0_tile^T      (rec, bf16x3)
//   Cx = h(t-1) @ Wih1_tile^T      (xg1 for time t-1, bf16x3, same A frags)
// xg1 overwrites g_xg slice [.., t-1, ..] (already consumed at step t-1).
// ---------------------------------------------------------------------------
__global__ void __launch_bounds__(256, 1) gru_rec0_fused_kernel(
    const float* __restrict__ Whh, const float* __restrict__ bhh,
    const float* __restrict__ Wih1, const float* __restrict__ bih1)
{
    extern __shared__ char smraw[];
    uint4* Wf   = (uint4*)smraw;                               // 12*32*32 uint4 = 192KB
    float* Csm  = (float*)(smraw + 12 * 32 * 32 * 16);         // 64 x CSTRIDE
    float* Hsm  = Csm + 64 * CSTRIDE;                          // 64 x HSTRIDE

    const int tid  = threadIdx.x;
    const int bid  = blockIdx.x;
    const int jt   = bid & 31, mt = bid >> 5;
    const int m0   = mt * 64, j0 = jt * 16;
    const int warp = tid >> 5, lane = tid & 31;
    const int wm   = warp >> 1, wn = warp & 1;   // 4 x 2 warp grid
    const int g    = lane >> 2, tg = lane & 3;
    const int m16  = mt * 4 + wm;
    const int ty   = tid >> 4, tx = tid & 15;
    const int ty4  = ty << 4 >> 2;               // (tid>>4)<<2
    const int j    = j0 + tx;

    // ---- Build W fragments: rec (slots 0..5), xg1 (slots 6..11) ----
    build_wfrag((uint32_t*)Wf, Whh,  j0, tid, 0);
    build_wfrag((uint32_t*)Wf, Wih1, j0, tid, 6);

    // ---- Zero h fragment buffer 0 for THIS group only ----
    {
        int idx = (bid & 31) * 256 + tid;
        size_t base = (size_t)mt * 4096;
        uint4 z = make_uint4(0, 0, 0, 0);
        if (idx < 4096) g_hfrag[0][0][base + idx] = z;
        else            g_hfrag[0][1][base + idx - 4096] = z;
    }

    const float bb0 = bhh[0 * H_ + j];
    const float bb1 = bhh[1 * H_ + j];
    const float bb2 = bhh[2 * H_ + j];

    // xg1 epilogue bias pairs (per nt): cols gcol, gcol+1
    float2 bx[3];
    int    gcolv[3];
#pragma unroll
    for (int nt = 0; nt < 3; nt++) {
        int n0c  = (wn * 3 + nt) * 8 + 2 * tg;
        int gate = n0c >> 4, jj = n0c & 15;
        int gcol = gate * H_ + j0 + jj;
        gcolv[nt] = gcol;
        bx[nt] = make_float2(bih1[gcol], bih1[gcol + 1]);
    }

    float hreg[4] = {0.f, 0.f, 0.f, 0.f};

    // prefetch xg(0)
    float xr[4], xz[4], xn[4];
#pragma unroll
    for (int i = 0; i < 4; i++) {
        size_t xb = ((size_t)(m0 + ty4 + i) * T_ + 0) * G3H + j;
        xr[i] = g_xg[xb]; xz[i] = g_xg[xb + H_]; xn[i] = g_xg[xb + 2 * H_];
    }

    group_barrier(mt);

    for (int t = 0; t < T_; t++) {
        const uint4* __restrict__ Ahi = g_hfrag[t & 1][0];
        const uint4* __restrict__ Alo = g_hfrag[t & 1][1];

        float C[3][4] = {};
        float Cx[3][4] = {};

#pragma unroll 2
        for (int ks = 0; ks < 32; ks++) {
            size_t fidx = ((size_t)(m16 * 32 + ks)) * 32 + lane;
            uint4 ahi = Ahi[fidx];
            uint4 alo = Alo[fidx];
#pragma unroll
            for (int nt = 0; nt < 3; nt++) {
                uint4 w = Wf[((wn * 3 + nt) * 32 + ks) * 32 + lane];
                mma_bf16(C[nt], ahi, w.x, w.y);
                mma_bf16(C[nt], ahi, w.z, w.w);
                mma_bf16(C[nt], alo, w.x, w.y);
            }
#pragma unroll
            for (int nt = 0; nt < 3; nt++) {
                uint4 w = Wf[((6 + wn * 3 + nt) * 32 + ks) * 32 + lane];
                mma_bf16(Cx[nt], ahi, w.x, w.y);
                mma_bf16(Cx[nt], ahi, w.z, w.w);
                mma_bf16(Cx[nt], alo, w.x, w.y);
            }
        }

        // ---- write xg1[t-1] straight from fragments (+bias) ----
        if (t > 0) {
            int mr = m0 + wm * 16 + g;
#pragma unroll
            for (int nt = 0; nt < 3; nt++) {
                float2 o0 = make_float2(Cx[nt][0] + bx[nt].x, Cx[nt][1] + bx[nt].y);
                float2 o1 = make_float2(Cx[nt][2] + bx[nt].x, Cx[nt][3] + bx[nt].y);
                *(float2*)(g_xg + ((size_t)mr * T_ + (t - 1)) * G3H + gcolv[nt])       = o0;
                *(float2*)(g_xg + ((size_t)(mr + 8) * T_ + (t - 1)) * G3H + gcolv[nt]) = o1;
            }
        }

        // ---- stage rec C to smem for gate math ----
#pragma unroll
        for (int nt = 0; nt < 3; nt++) {
            int cbase = (wn * 3 + nt) * 8 + 2 * tg;
            int r0 = wm * 16 + g;
            *(float2*)&Csm[r0 * CSTRIDE + cbase]       = make_float2(C[nt][0], C[nt][1]);
            *(float2*)&Csm[(r0 + 8) * CSTRIDE + cbase] = make_float2(C[nt][2], C[nt][3]);
        }
        __syncthreads();

        // ---- gate update: 4 outputs per thread; stage hnew in smem ----
#pragma unroll
        for (int i = 0; i < 4; i++) {
            int ml = ty4 + i;
            float cr = Csm[ml * CSTRIDE + tx];
            float cz = Csm[ml * CSTRIDE + 16 + tx];
            float cn = Csm[ml * CSTRIDE + 32 + tx];

            float r = 1.0f / (1.0f + expf(-(xr[i] + cr + bb0)));
            float z = 1.0f / (1.0f + expf(-(xz[i] + cz + bb1)));
            float n = tanhf(xn[i] + r * (cn + bb2));

            float hnew = (1.0f - z) * n + z * hreg[i];
            hreg[i] = hnew;
            Hsm[ml * HSTRIDE + tx] = hnew;
        }
        __syncthreads();

        // ---- pack h fragments: 128 threads, coalesced uint4 stores ----
        if (tid < 128) {
            const int m16l = tid >> 5;
            const int ln   = tid & 31;
            const int gg   = ln >> 2, tg2 = ln & 3;
            const int r0 = m16l * 16 + gg, r1 = r0 + 8;
            const int k0 = tg2 * 2;

            float v[8];
            v[0] = Hsm[r0 * HSTRIDE + k0];     v[1] = Hsm[r0 * HSTRIDE + k0 + 1];
            v[2] = Hsm[r1 * HSTRIDE + k0];     v[3] = Hsm[r1 * HSTRIDE + k0 + 1];
            v[4] = Hsm[r0 * HSTRIDE + k0 + 8]; v[5] = Hsm[r0 * HSTRIDE + k0 + 9];
            v[6] = Hsm[r1 * HSTRIDE + k0 + 8]; v[7] = Hsm[r1 * HSTRIDE + k0 + 9];

            float fh[8], fl[8];
#pragma unroll
            for (int q = 0; q < 8; q++) {
                fh[q] = __bfloat162float(__float2bfloat16(v[q]));
                fl[q] = v[q] - fh[q];
            }
            uint4 hi, lo;
            hi.x = pack2_bf16(fh[0], fh[1]); hi.y = pack2_bf16(fh[2], fh[3]);
            hi.z = pack2_bf16(fh[4], fh[5]); hi.w = pack2_bf16(fh[6], fh[7]);
            lo.x = pack2_bf16(fl[0], fl[1]); lo.y = pack2_bf16(fl[2], fl[3]);
            lo.z = pack2_bf16(fl[4], fl[5]); lo.w = pack2_bf16(fl[6], fl[7]);

            const int nb = (t + 1) & 1;
            size_t base = ((size_t)((mt * 4 + m16l) * 32 + jt)) * 32 + ln;
            g_hfrag[nb][0][base] = hi;
            g_hfrag[nb][1][base] = lo;
        }

        // prefetch xg(t+1) BEFORE the barrier (independent of h(t))
        if (t < T_ - 1) {
#pragma unroll
            for (int i = 0; i < 4; i++) {
                size_t xb = ((size_t)(m0 + ty4 + i) * T_ + (t + 1)) * G3H + j;
                xr[i] = g_xg[xb]; xz[i] = g_xg[xb + H_]; xn[i] = g_xg[xb + 2 * H_];
            }
        }

        group_barrier(mt);
    }

    // ---- tail: xg1[255] from h(255) (fragments in buffer 0, visible) ----
    {
        const uint4* __restrict__ Ahi = g_hfrag[0][0];
        const uint4* __restrict__ Alo = g_hfrag[0][1];
        float Cx[3][4] = {};
#pragma unroll 2
        for (int ks = 0; ks < 32; ks++) {
            size_t fidx = ((size_t)(m16 * 32 + ks)) * 32 + lane;
            uint4 ahi = Ahi[fidx];
            uint4 alo = Alo[fidx];
#pragma unroll
            for (int nt = 0; nt < 3; nt++) {
                uint4 w = Wf[((6 + wn * 3 + nt) * 32 + ks) * 32 + lane];
                mma_bf16(Cx[nt], ahi, w.x, w.y);
                mma_bf16(Cx[nt], ahi, w.z, w.w);
                mma_bf16(Cx[nt], alo, w.x, w.y);
            }
        }
        int mr = m0 + wm * 16 + g;
#pragma unroll
        for (int nt = 0; nt < 3; nt++) {
            float2 o0 = make_float2(Cx[nt][0] + bx[nt].x, Cx[nt][1] + bx[nt].y);
            float2 o1 = make_float2(Cx[nt][2] + bx[nt].x, Cx[nt][3] + bx[nt].y);
            *(float2*)(g_xg + ((size_t)mr * T_ + (T_ - 1)) * G3H + gcolv[nt])       = o0;
            *(float2*)(g_xg + ((size_t)(mr + 8) * T_ + (T_ - 1)) * G3H + gcolv[nt]) = o1;
        }
    }
}

// ---------------------------------------------------------------------------
// Layer-1 recurrence (reads xg1 from g_xg; writes final hidden to g_hT)
// ---------------------------------------------------------------------------
__global__ void __launch_bounds__(256, 1) gru_rec1_kernel(
    const float* __restrict__ Whh, const float* __restrict__ bhh)
{
    extern __shared__ char smraw[];
    uint4* Wf   = (uint4*)smraw;                              // 6*32*32 uint4 = 96KB
    float* Csm  = (float*)(smraw + 6 * 32 * 32 * 16);
    float* Hsm  = Csm + 64 * CSTRIDE;

    const int tid  = threadIdx.x;
    const int bid  = blockIdx.x;
    const int jt   = bid & 31, mt = bid >> 5;
    const int m0   = mt * 64, j0 = jt * 16;
    const int warp = tid >> 5, lane = tid & 31;
    const int wm   = warp >> 1, wn = warp & 1;
    const int g    = lane >> 2, tg = lane & 3;
    const int m16  = mt * 4 + wm;
    const int ty   = tid >> 4, tx = tid & 15;
    const int ty4  = ty << 2;
    const int j    = j0 + tx;

    build_wfrag((uint32_t*)Wf, Whh, j0, tid, 0);

    {
        int idx = (bid & 31) * 256 + tid;
        size_t base = (size_t)mt * 4096;
        uint4 z = make_uint4(0, 0, 0, 0);
        if (idx < 4096) g_hfrag[0][0][base + idx] = z;
        else            g_hfrag[0][1][base + idx - 4096] = z;
    }

    const float bb0 = bhh[0 * H_ + j];
    const float bb1 = bhh[1 * H_ + j];
    const float bb2 = bhh[2 * H_ + j];

    float hreg[4] = {0.f, 0.f, 0.f, 0.f};

    float xr[4], xz[4], xn[4];
#pragma unroll
    for (int i = 0; i < 4; i++) {
        size_t xb = ((size_t)(m0 + ty4 + i) * T_ + 0) * G3H + j;
        xr[i] = g_xg[xb]; xz[i] = g_xg[xb + H_]; xn[i] = g_xg[xb + 2 * H_];
    }

    group_barrier(mt);

    for (int t = 0; t < T_; t++) {
        const uint4* __restrict__ Ahi = g_hfrag[t & 1][0];
        const uint4* __restrict__ Alo = g_hfrag[t & 1][1];

        float C[3][4] = {};

#pragma unroll 4
        for (int ks = 0; ks < 32; ks++) {
            size_t fidx = ((size_t)(m16 * 32 + ks)) * 32 + lane;
            uint4 ahi = Ahi[fidx];
            uint4 alo = Alo[fidx];
#pragma unroll
            for (int nt = 0; nt < 3; nt++) {
                uint4 w = Wf[((wn * 3 + nt) * 32 + ks) * 32 + lane];
                mma_bf16(C[nt], ahi, w.x, w.y);
                mma_bf16(C[nt], ahi, w.z, w.w);
                mma_bf16(C[nt], alo, w.x, w.y);
            }
        }

#pragma unroll
        for (int nt = 0; nt < 3; nt++) {
            int cbase = (wn * 3 + nt) * 8 + 2 * tg;
            int r0 = wm * 16 + g;
            *(float2*)&Csm[r0 * CSTRIDE + cbase]       = make_float2(C[nt][0], C[nt][1]);
            *(float2*)&Csm[(r0 + 8) * CSTRIDE + cbase] = make_float2(C[nt][2], C[nt][3]);
        }
        __syncthreads();

#pragma unroll
        for (int i = 0; i < 4; i++) {
            int ml = ty4 + i;
            float cr = Csm[ml * CSTRIDE + tx];
            float cz = Csm[ml * CSTRIDE + 16 + tx];
            float cn = Csm[ml * CSTRIDE + 32 + tx];

            float r = 1.0f / (1.0f + expf(-(xr[i] + cr + bb0)));
            float z = 1.0f / (1.0f + expf(-(xz[i] + cz + bb1)));
            float n = tanhf(xn[i] + r * (cn + bb2));

            float hnew = (1.0f - z) * n + z * hreg[i];
            hreg[i] = hnew;
            Hsm[ml * HSTRIDE + tx] = hnew;

            if (t == T_ - 1) {
                g_hT[(size_t)(m0 + ml) * H_ + j] = hnew;
            }
        }
        __syncthreads();

        if (tid < 128 && t < T_ - 1) {
            const int m16l = tid >> 5;
            const int ln   = tid & 31;
            const int gg   = ln >> 2, tg2 = ln & 3;
            const int r0 = m16l * 16 + gg, r1 = r0 + 8;
            const int k0 = tg2 * 2;

            float v[8];
            v[0] = Hsm[r0 * HSTRIDE + k0];     v[1] = Hsm[r0 * HSTRIDE + k0 + 1];
            v[2] = Hsm[r1 * HSTRIDE + k0];     v[3] = Hsm[r1 * HSTRIDE + k0 + 1];
            v[4] = Hsm[r0 * HSTRIDE + k0 + 8]; v[5] = Hsm[r0 * HSTRIDE + k0 + 9];
            v[6] = Hsm[r1 * HSTRIDE + k0 + 8]; v[7] = Hsm[r1 * HSTRIDE + k0 + 9];

            float fh[8], fl[8];
#pragma unroll
            for (int q = 0; q < 8; q++) {
                fh[q] = __bfloat162float(__float2bfloat16(v[q]));
                fl[q] = v[q] - fh[q];
            }
            uint4 hi, lo;
            hi.x = pack2_bf16(fh[0], fh[1]); hi.y = pack2_bf16(fh[2], fh[3]);
            hi.z = pack2_bf16(fh[4], fh[5]); hi.w = pack2_bf16(fh[6], fh[7]);
            lo.x = pack2_bf16(fl[0], fl[1]); lo.y = pack2_bf16(fl[2], fl[3]);
            lo.z = pack2_bf16(fl[4], fl[5]); lo.w = pack2_bf16(fl[6], fl[7]);

            const int nb = (t + 1) & 1;
            size_t base = ((size_t)((mt * 4 + m16l) * 32 + jt)) * 32 + ln;
            g_hfrag[nb][0][base] = hi;
            g_hfrag[nb][1][base] = lo;
        }

        if (t < T_ - 1) {
#pragma unroll
            for (int i = 0; i < 4; i++) {
                size_t xb = ((size_t)(m0 + ty4 + i) * T_ + (t + 1)) * G3H + j;
                xr[i] = g_xg[xb]; xz[i] = g_xg[xb + H_]; xn[i] = g_xg[xb + 2 * H_];
            }
            group_barrier(mt);
        }
    }
}

// ---------------------------------------------------------------------------
// Head: out = relu(relu(hT) @ fc1^T + b1) @ fc2^T + b2
// ---------------------------------------------------------------------------
__global__ void __launch_bounds__(128) head_kernel(
    const float* __restrict__ w1, const float* __restrict__ b1,
    const float* __restrict__ w2, const float* __restrict__ b2,
    float* __restrict__ out)
{
    __shared__ float sh[H_];
    __shared__ float s1[128];
    const int b = blockIdx.x;
    const int tid = threadIdx.x;

#pragma unroll
    for (int r = 0; r < 4; r++) {
        float v = g_hT[(size_t)b * H_ + tid + r * 128];
        sh[tid + r * 128] = fmaxf(v, 0.0f);
    }
    __syncthreads();

    float acc = b1[tid];
    const float* wrow = w1 + (size_t)tid * H_;
#pragma unroll 8
    for (int jj = 0; jj < H_; jj++) acc = fmaf(sh[jj], __ldg(wrow + jj), acc);
    s1[tid] = fmaxf(acc, 0.0f);
    __syncthreads();

    if (tid < 10) {
        float a = b2[tid];
        const float* w2row = w2 + (size_t)tid * 128;
#pragma unroll 8
        for (int i = 0; i < 128; i++) a = fmaf(s1[i], __ldg(w2row + i), a);
        out[(size_t)b * 10 + tid] = a;
    }
}

// ---------------------------------------------------------------------------
// Launch
// ---------------------------------------------------------------------------
extern "C" void kernel_launch(void* const* d_in, const int* in_sizes, int n_in,
                              void* d_out, int out_size)
{
    const float* x    = (const float*)d_in[0];
    const float* Wih0 = (const float*)d_in[1];
    const float* Whh0 = (const float*)d_in[2];
    const float* bih0 = (const float*)d_in[3];
    const float* bhh0 = (const float*)d_in[4];
    const float* Wih1 = (const float*)d_in[5];
    const float* Whh1 = (const float*)d_in[6];
    const float* bih1 = (const float*)d_in[7];
    const float* bhh1 = (const float*)d_in[8];
    const float* fc1w = (const float*)d_in[9];
    const float* fc1b = (const float*)d_in[10];
    const float* fc2w = (const float*)d_in[11];
    const float* fc2b = (const float*)d_in[12];
    float* out = (float*)d_out;

    float* xg_ptr = nullptr;
    cudaGetSymbolAddress((void**)&xg_ptr, g_xg);

    const int rec0_smem = 12 * 32 * 32 * 16 + (64 * CSTRIDE + 64 * HSTRIDE) * 4;
    const int rec1_smem = 6 * 32 * 32 * 16 + (64 * CSTRIDE + 64 * HSTRIDE) * 4;
    cudaFuncSetAttribute((const void*)gru_rec0_fused_kernel,
                         cudaFuncAttributeMaxDynamicSharedMemorySize, rec0_smem);
    cudaFuncSetAttribute((const void*)gru_rec1_kernel,
                         cudaFuncAttributeMaxDynamicSharedMemorySize, rec1_smem);

    dim3 gemm_grid(G3H / 128, BT / 128);  // (12, 512)

    // Phase 1: xg0 = x @ W_ih0^T + b_ih0   (K = 128)
    gemm_tf32_kernel<<<gemm_grid, 256>>>(x, Wih0, bih0, D_, xg_ptr);

    // Phase 2: fused layer-0 recurrence + layer-1 input projection
    gru_rec0_fused_kernel<<<128, 256, rec0_smem>>>(Whh0, bhh0, Wih1, bih1);

    // Phase 3: layer-1 recurrence
    gru_rec1_kernel<<<128, 256, rec1_smem>>>(Whh1, bhh1);

    // Phase 4: MLP head
    head_kernel<<<B_, 128>>>(fc1w, fc1b, fc2w, fc2b, out);
}

// round 6
// speedup vs baseline: 3.4162x; 1.0657x over previous
#include <cuda_runtime.h>
#include <cuda_bf16.h>
#include <math.h>
#include <stdint.h>

// Problem dims (fixed by the dataset)
#define B_   256
#define T_   256
#define D_   128
#define H_   512
#define G3H  1536
#define BT   (B_ * T_)

// ---------------------------------------------------------------------------
// Scratch (static device allocations; harness forbids cudaMalloc)
// ---------------------------------------------------------------------------
__device__ float g_xg[(size_t)BT * G3H];   // 402 MB: xg0, overwritten in-place by xg1
__device__ float g_hT[B_ * H_];            // final hidden of layer 1
// h in A-fragment order, bf16 hi/lo, double buffered:
// [buf][hi=0/lo=1][ (m16*32 + ks)*32 + lane ], each uint4 = regs a0..a3
__device__ uint4 g_hfrag[2][2][16 * 32 * 32];

// per-mt-group barrier slots, 128B padded
struct BarSlot { unsigned cnt; volatile unsigned gen; unsigned pad[30]; };
__device__ BarSlot g_bar[4];

// ---------------------------------------------------------------------------
// Group barrier: 32 blocks sharing one mt group. Tight spin.
// ---------------------------------------------------------------------------
__device__ __forceinline__ void group_barrier(int grp) {
    __syncthreads();
    if (threadIdx.x == 0) {
        __threadfence();
        unsigned gen = g_bar[grp].gen;      // read BEFORE arriving
        if (atomicAdd(&g_bar[grp].cnt, 1u) == 31u) {
            atomicExch(&g_bar[grp].cnt, 0u);
            __threadfence();
            g_bar[grp].gen = gen + 1u;
        } else {
            while (g_bar[grp].gen == gen) { }
        }
        __threadfence();
    }
    __syncthreads();
}

// ---------------------------------------------------------------------------
// tf32 helpers (projection GEMM)
// ---------------------------------------------------------------------------
__device__ __forceinline__ uint32_t f2tf(float f) {
    uint32_t u;
    asm("cvt.rna.tf32.f32 %0, %1;" : "=r"(u) : "f"(f));
    return u;
}

__device__ __forceinline__ void mma_tf32(float* c, const uint32_t* a, const uint32_t* b) {
    asm volatile(
        "mma.sync.aligned.m16n8k8.row.col.f32.tf32.tf32.f32 "
        "{%0,%1,%2,%3}, {%4,%5,%6,%7}, {%8,%9}, {%0,%1,%2,%3};\n"
        : "+f"(c[0]), "+f"(c[1]), "+f"(c[2]), "+f"(c[3])
        : "r"(a[0]), "r"(a[1]), "r"(a[2]), "r"(a[3]), "r"(b[0]), "r"(b[1]));
}

// bf16 mma m16n8k16, fp32 accum
__device__ __forceinline__ void mma_bf16(float* c, const uint4& a, uint32_t b0, uint32_t b1) {
    asm volatile(
        "mma.sync.aligned.m16n8k16.row.col.f32.bf16.bf16.f32 "
        "{%0,%1,%2,%3}, {%4,%5,%6,%7}, {%8,%9}, {%0,%1,%2,%3};\n"
        : "+f"(c[0]), "+f"(c[1]), "+f"(c[2]), "+f"(c[3])
        : "r"(a.x), "r"(a.y), "r"(a.z), "r"(a.w), "r"(b0), "r"(b1));
}

__device__ __forceinline__ uint32_t pack2_bf16(float e0, float e1) {
    __nv_bfloat162 t = __floats2bfloat162_rn(e0, e1);  // .x = low half
    return *(uint32_t*)&t;
}

// Build bf16 hi/lo B-fragments for a 48-col (3 gates x 16) x 512-k weight tile.
__device__ __forceinline__ void build_wfrag(
    uint32_t* Wu, const float* __restrict__ Wsrc, int j0, int tid, int slot_off, int nthreads)
{
    for (int idx = tid; idx < 48 * 256; idx += nthreads) {
        int n  = idx >> 8;
        int k  = (idx & 255) << 1;
        int gate = n >> 4, jj = n & 15;
        const float* wrow = Wsrc + ((size_t)(gate * H_ + j0 + jj)) * H_;
        float w0 = wrow[k], w1 = wrow[k + 1];
        float h0 = __bfloat162float(__float2bfloat16(w0));
        float h1 = __bfloat162float(__float2bfloat16(w1));
        uint32_t hi = pack2_bf16(h0, h1);
        uint32_t lo = pack2_bf16(w0 - h0, w1 - h1);
        int nt = (n >> 3) + slot_off;
        int ks = k >> 4, kr = k & 15;
        int rr   = (kr >= 8) ? 1 : 0;
        int lw   = (n & 7) * 4 + ((kr >> 1) & 3);
        int base = (((nt * 32 + ks) * 32 + lw) << 2);
        Wu[base + rr]     = hi;
        Wu[base + 2 + rr] = lo;
    }
}

// ---------------------------------------------------------------------------
// tf32 tensor-core GEMM: C[M, 1536] = A[M, K] @ W[1536, K]^T + bias (phase 1)
// ---------------------------------------------------------------------------
__global__ void __launch_bounds__(256) gemm_tf32_kernel(
    const float* __restrict__ A, const float* __restrict__ W,
    const float* __restrict__ bias, int K, float* __restrict__ C)
{
    __shared__ uint32_t As[128][36];
    __shared__ uint32_t Bs[128][36];

    const int tid  = threadIdx.x;
    const int m0   = blockIdx.y * 128;
    const int n0   = blockIdx.x * 128;
    const int warp = tid >> 5, lane = tid & 31;
    const int wm = warp >> 2, wn = warp & 3;
    const int g  = lane >> 2, tg = lane & 3;

    float acc[4][4][4] = {};

    for (int k0 = 0; k0 < K; k0 += 32) {
#pragma unroll
        for (int r = 0; r < 4; r++) {
            int f   = tid + (r << 8);
            int row = f >> 3;
            int c4  = (f & 7) << 2;
            float4 va = *(const float4*)(A + (size_t)(m0 + row) * K + k0 + c4);
            As[row][c4 + 0] = f2tf(va.x);
            As[row][c4 + 1] = f2tf(va.y);
            As[row][c4 + 2] = f2tf(va.z);
            As[row][c4 + 3] = f2tf(va.w);
            float4 vb = *(const float4*)(W + (size_t)(n0 + row) * K + k0 + c4);
            Bs[row][c4 + 0] = f2tf(vb.x);
            Bs[row][c4 + 1] = f2tf(vb.y);
            Bs[row][c4 + 2] = f2tf(vb.z);
            Bs[row][c4 + 3] = f2tf(vb.w);
        }
        __syncthreads();

#pragma unroll
        for (int s = 0; s < 4; s++) {
            const int kb = s << 3;
            uint32_t a[4][4], b[4][2];
#pragma unroll
            for (int i = 0; i < 4; i++) {
                int r0 = wm * 64 + i * 16 + g;
                a[i][0] = As[r0][kb + tg];
                a[i][1] = As[r0 + 8][kb + tg];
                a[i][2] = As[r0][kb + tg + 4];
                a[i][3] = As[r0 + 8][kb + tg + 4];
            }
#pragma unroll
            for (int jx = 0; jx < 4; jx++) {
                int c = wn * 32 + jx * 8 + g;
                b[jx][0] = Bs[c][kb + tg];
                b[jx][1] = Bs[c][kb + tg + 4];
            }
#pragma unroll
            for (int i = 0; i < 4; i++)
#pragma unroll
                for (int jx = 0; jx < 4; jx++)
                    mma_tf32(acc[i][jx], a[i], b[jx]);
        }
        __syncthreads();
    }

#pragma unroll
    for (int i = 0; i < 4; i++) {
        int r0 = m0 + wm * 64 + i * 16 + g;
#pragma unroll
        for (int jx = 0; jx < 4; jx++) {
            int col = n0 + wn * 32 + jx * 8 + tg * 2;
            float2 bv = *(const float2*)(bias + col);
            float2 o0 = make_float2(acc[i][jx][0] + bv.x, acc[i][jx][1] + bv.y);
            float2 o1 = make_float2(acc[i][jx][2] + bv.x, acc[i][jx][3] + bv.y);
            *(float2*)(C + (size_t)r0 * G3H + col)       = o0;
            *(float2*)(C + (size_t)(r0 + 8) * G3H + col) = o1;
        }
    }
}

#define CSTRIDE 50
#define HSTRIDE 17

// ---------------------------------------------------------------------------
// Shared epilogue pieces
// ---------------------------------------------------------------------------
__device__ __forceinline__ void pack_hfrag(
    const float* Hsm, int mt, int jt, int t, int tid)
{
    if (tid < 128) {
        const int m16l = tid >> 5;
        const int ln   = tid & 31;
        const int gg   = ln >> 2, tg2 = ln & 3;
        const int r0 = m16l * 16 + gg, r1 = r0 + 8;
        const int k0 = tg2 * 2;

        float v[8];
        v[0] = Hsm[r0 * HSTRIDE + k0];     v[1] = Hsm[r0 * HSTRIDE + k0 + 1];
        v[2] = Hsm[r1 * HSTRIDE + k0];     v[3] = Hsm[r1 * HSTRIDE + k0 + 1];
        v[4] = Hsm[r0 * HSTRIDE + k0 + 8]; v[5] = Hsm[r0 * HSTRIDE + k0 + 9];
        v[6] = Hsm[r1 * HSTRIDE + k0 + 8]; v[7] = Hsm[r1 * HSTRIDE + k0 + 9];

        float fh[8], fl[8];
#pragma unroll
        for (int q = 0; q < 8; q++) {
            fh[q] = __bfloat162float(__float2bfloat16(v[q]));
            fl[q] = v[q] - fh[q];
        }
        uint4 hi, lo;
        hi.x = pack2_bf16(fh[0], fh[1]); hi.y = pack2_bf16(fh[2], fh[3]);
        hi.z = pack2_bf16(fh[4], fh[5]); hi.w = pack2_bf16(fh[6], fh[7]);
        lo.x = pack2_bf16(fl[0], fl[1]); lo.y = pack2_bf16(fl[2], fl[3]);
        lo.z = pack2_bf16(fl[4], fl[5]); lo.w = pack2_bf16(fl[6], fl[7]);

        const int nb = (t + 1) & 1;
        size_t base = ((size_t)((mt * 4 + m16l) * 32 + jt)) * 32 + ln;
        g_hfrag[nb][0][base] = hi;
        g_hfrag[nb][1][base] = lo;
    }
}

// ---------------------------------------------------------------------------
// FUSED layer-0 recurrence + layer-1 input projection. 512 threads, task-split:
// warps 0-7 do the recurrent GEMM, warps 8-15 do the xg1 GEMM (same A frags).
// ---------------------------------------------------------------------------
__global__ void __launch_bounds__(512, 1) gru_rec0_fused_kernel(
    const float* __restrict__ Whh, const float* __restrict__ bhh,
    const float* __restrict__ Wih1, const float* __restrict__ bih1)
{
    extern __shared__ char smraw[];
    uint4* Wf   = (uint4*)smraw;                               // 12*32*32 uint4 = 192KB
    float* Csm  = (float*)(smraw + 12 * 32 * 32 * 16);         // 64 x CSTRIDE
    float* Hsm  = Csm + 64 * CSTRIDE;                          // 64 x HSTRIDE

    const int tid  = threadIdx.x;
    const int bid  = blockIdx.x;
    const int jt   = bid & 31, mt = bid >> 5;
    const int m0   = mt * 64, j0 = jt * 16;
    const int w    = tid >> 5, lane = tid & 31;
    const int task = w >> 3;                    // 0 = rec, 1 = xg1
    const int wm   = (w >> 1) & 3, wn = w & 1;
    const int g    = lane >> 2, tg = lane & 3;
    const int m16  = mt * 4 + wm;
    const int tx   = tid & 15;
    const int row2 = (tid >> 4) << 1;           // 0..62, 2 rows per thread
    const int j    = j0 + tx;

    build_wfrag((uint32_t*)Wf, Whh,  j0, tid, 0, 512);
    build_wfrag((uint32_t*)Wf, Wih1, j0, tid, 6, 512);

    // ---- Zero h fragment buffer 0 for THIS group only ----
    {
        int idx = (bid & 31) * 512 + tid;
        size_t base = (size_t)mt * 4096;
        uint4 z = make_uint4(0, 0, 0, 0);
        if (idx < 4096)      g_hfrag[0][0][base + idx] = z;
        else if (idx < 8192) g_hfrag[0][1][base + idx - 4096] = z;
    }

    const float bb0 = bhh[j];
    const float bb1 = bhh[H_ + j];
    const float bb2 = bhh[2 * H_ + j];

    // xg1 epilogue bias pairs (used by task-1 warps)
    float2 bx[3];
    int    gcolv[3];
#pragma unroll
    for (int nt = 0; nt < 3; nt++) {
        int n0c  = (wn * 3 + nt) * 8 + 2 * tg;
        int gate = n0c >> 4, jj = n0c & 15;
        int gcol = gate * H_ + j0 + jj;
        gcolv[nt] = gcol;
        bx[nt] = make_float2(bih1[gcol], bih1[gcol + 1]);
    }

    float hreg[2] = {0.f, 0.f};

    float xr[2], xz[2], xn[2];
#pragma unroll
    for (int i = 0; i < 2; i++) {
        size_t xb = ((size_t)(m0 + row2 + i) * T_ + 0) * G3H + j;
        xr[i] = g_xg[xb]; xz[i] = g_xg[xb + H_]; xn[i] = g_xg[xb + 2 * H_];
    }

    group_barrier(mt);

    for (int t = 0; t < T_; t++) {
        const uint4* __restrict__ Ahi = g_hfrag[t & 1][0];
        const uint4* __restrict__ Alo = g_hfrag[t & 1][1];

        if (task == 0) {
            float C[3][4] = {};
#pragma unroll 4
            for (int ks = 0; ks < 32; ks++) {
                size_t fidx = ((size_t)(m16 * 32 + ks)) * 32 + lane;
                uint4 ahi = Ahi[fidx];
                uint4 alo = Alo[fidx];
#pragma unroll
                for (int nt = 0; nt < 3; nt++) {
                    uint4 wf = Wf[((wn * 3 + nt) * 32 + ks) * 32 + lane];
                    mma_bf16(C[nt], ahi, wf.x, wf.y);
                    mma_bf16(C[nt], ahi, wf.z, wf.w);
                    mma_bf16(C[nt], alo, wf.x, wf.y);
                }
            }
#pragma unroll
            for (int nt = 0; nt < 3; nt++) {
                int cbase = (wn * 3 + nt) * 8 + 2 * tg;
                int r0 = wm * 16 + g;
                *(float2*)&Csm[r0 * CSTRIDE + cbase]       = make_float2(C[nt][0], C[nt][1]);
                *(float2*)&Csm[(r0 + 8) * CSTRIDE + cbase] = make_float2(C[nt][2], C[nt][3]);
            }
        } else {
            float Cx[3][4] = {};
#pragma unroll 4
            for (int ks = 0; ks < 32; ks++) {
                size_t fidx = ((size_t)(m16 * 32 + ks)) * 32 + lane;
                uint4 ahi = Ahi[fidx];
                uint4 alo = Alo[fidx];
#pragma unroll
                for (int nt = 0; nt < 3; nt++) {
                    uint4 wf = Wf[((6 + wn * 3 + nt) * 32 + ks) * 32 + lane];
                    mma_bf16(Cx[nt], ahi, wf.x, wf.y);
                    mma_bf16(Cx[nt], ahi, wf.z, wf.w);
                    mma_bf16(Cx[nt], alo, wf.x, wf.y);
                }
            }
            if (t > 0) {
                int mr = m0 + wm * 16 + g;
#pragma unroll
                for (int nt = 0; nt < 3; nt++) {
                    float2 o0 = make_float2(Cx[nt][0] + bx[nt].x, Cx[nt][1] + bx[nt].y);
                    float2 o1 = make_float2(Cx[nt][2] + bx[nt].x, Cx[nt][3] + bx[nt].y);
                    *(float2*)(g_xg + ((size_t)mr * T_ + (t - 1)) * G3H + gcolv[nt])       = o0;
                    *(float2*)(g_xg + ((size_t)(mr + 8) * T_ + (t - 1)) * G3H + gcolv[nt]) = o1;
                }
            }
        }
        __syncthreads();

        // ---- gate update: 2 outputs per thread ----
#pragma unroll
        for (int i = 0; i < 2; i++) {
            int ml = row2 + i;
            float cr = Csm[ml * CSTRIDE + tx];
            float cz = Csm[ml * CSTRIDE + 16 + tx];
            float cn = Csm[ml * CSTRIDE + 32 + tx];

            float r = 1.0f / (1.0f + expf(-(xr[i] + cr + bb0)));
            float z = 1.0f / (1.0f + expf(-(xz[i] + cz + bb1)));
            float n = tanhf(xn[i] + r * (cn + bb2));

            float hnew = (1.0f - z) * n + z * hreg[i];
            hreg[i] = hnew;
            Hsm[ml * HSTRIDE + tx] = hnew;
        }
        __syncthreads();

        pack_hfrag(Hsm, mt, jt, t, tid);

        if (t < T_ - 1) {
#pragma unroll
            for (int i = 0; i < 2; i++) {
                size_t xb = ((size_t)(m0 + row2 + i) * T_ + (t + 1)) * G3H + j;
                xr[i] = g_xg[xb]; xz[i] = g_xg[xb + H_]; xn[i] = g_xg[xb + 2 * H_];
            }
        }

        group_barrier(mt);
    }

    // ---- tail: xg1[255] from h(255) (fragments in buffer 0) ----
    if (task == 1) {
        const uint4* __restrict__ Ahi = g_hfrag[0][0];
        const uint4* __restrict__ Alo = g_hfrag[0][1];
        float Cx[3][4] = {};
#pragma unroll 4
        for (int ks = 0; ks < 32; ks++) {
            size_t fidx = ((size_t)(m16 * 32 + ks)) * 32 + lane;
            uint4 ahi = Ahi[fidx];
            uint4 alo = Alo[fidx];
#pragma unroll
            for (int nt = 0; nt < 3; nt++) {
                uint4 wf = Wf[((6 + wn * 3 + nt) * 32 + ks) * 32 + lane];
                mma_bf16(Cx[nt], ahi, wf.x, wf.y);
                mma_bf16(Cx[nt], ahi, wf.z, wf.w);
                mma_bf16(Cx[nt], alo, wf.x, wf.y);
            }
        }
        int mr = m0 + wm * 16 + g;
#pragma unroll
        for (int nt = 0; nt < 3; nt++) {
            float2 o0 = make_float2(Cx[nt][0] + bx[nt].x, Cx[nt][1] + bx[nt].y);
            float2 o1 = make_float2(Cx[nt][2] + bx[nt].x, Cx[nt][3] + bx[nt].y);
            *(float2*)(g_xg + ((size_t)mr * T_ + (T_ - 1)) * G3H + gcolv[nt])       = o0;
            *(float2*)(g_xg + ((size_t)(mr + 8) * T_ + (T_ - 1)) * G3H + gcolv[nt]) = o1;
        }
    }
}

// ---------------------------------------------------------------------------
// Layer-1 recurrence. 512 threads, k-split: warp (wm, wn, wk) computes its
// (m16, n24) tile over k-half wk; partials staged in two Csm buffers, summed
// in the gate epilogue.
// ---------------------------------------------------------------------------
__global__ void __launch_bounds__(512, 1) gru_rec1_kernel(
    const float* __restrict__ Whh, const float* __restrict__ bhh)
{
    extern __shared__ char smraw[];
    uint4* Wf   = (uint4*)smraw;                              // 6*32*32 uint4 = 96KB
    float* Csm  = (float*)(smraw + 6 * 32 * 32 * 16);         // 2 x 64 x CSTRIDE
    float* Hsm  = Csm + 2 * 64 * CSTRIDE;

    const int tid  = threadIdx.x;
    const int bid  = blockIdx.x;
    const int jt   = bid & 31, mt = bid >> 5;
    const int m0   = mt * 64, j0 = jt * 16;
    const int w    = tid >> 5, lane = tid & 31;
    const int wm   = (w >> 2) & 3, wn = (w >> 1) & 1, wk = w & 1;
    const int g    = lane >> 2, tg = lane & 3;
    const int m16  = mt * 4 + wm;
    const int tx   = tid & 15;
    const int row2 = (tid >> 4) << 1;
    const int j    = j0 + tx;

    build_wfrag((uint32_t*)Wf, Whh, j0, tid, 0, 512);

    {
        int idx = (bid & 31) * 512 + tid;
        size_t base = (size_t)mt * 4096;
        uint4 z = make_uint4(0, 0, 0, 0);
        if (idx < 4096)      g_hfrag[0][0][base + idx] = z;
        else if (idx < 8192) g_hfrag[0][1][base + idx - 4096] = z;
    }

    const float bb0 = bhh[j];
    const float bb1 = bhh[H_ + j];
    const float bb2 = bhh[2 * H_ + j];

    float hreg[2] = {0.f, 0.f};

    float xr[2], xz[2], xn[2];
#pragma unroll
    for (int i = 0; i < 2; i++) {
        size_t xb = ((size_t)(m0 + row2 + i) * T_ + 0) * G3H + j;
        xr[i] = g_xg[xb]; xz[i] = g_xg[xb + H_]; xn[i] = g_xg[xb + 2 * H_];
    }

    group_barrier(mt);

    for (int t = 0; t < T_; t++) {
        const uint4* __restrict__ Ahi = g_hfrag[t & 1][0];
        const uint4* __restrict__ Alo = g_hfrag[t & 1][1];

        float C[3][4] = {};
        const int ks0 = wk << 4;
#pragma unroll 4
        for (int kk = 0; kk < 16; kk++) {
            int ks = ks0 + kk;
            size_t fidx = ((size_t)(m16 * 32 + ks)) * 32 + lane;
            uint4 ahi = Ahi[fidx];
            uint4 alo = Alo[fidx];
#pragma unroll
            for (int nt = 0; nt < 3; nt++) {
                uint4 wf = Wf[((wn * 3 + nt) * 32 + ks) * 32 + lane];
                mma_bf16(C[nt], ahi, wf.x, wf.y);
                mma_bf16(C[nt], ahi, wf.z, wf.w);
                mma_bf16(C[nt], alo, wf.x, wf.y);
            }
        }

        float* Cb = Csm + wk * (64 * CSTRIDE);
#pragma unroll
        for (int nt = 0; nt < 3; nt++) {
            int cbase = (wn * 3 + nt) * 8 + 2 * tg;
            int r0 = wm * 16 + g;
            *(float2*)&Cb[r0 * CSTRIDE + cbase]       = make_float2(C[nt][0], C[nt][1]);
            *(float2*)&Cb[(r0 + 8) * CSTRIDE + cbase] = make_float2(C[nt][2], C[nt][3]);
        }
        __syncthreads();

#pragma unroll
        for (int i = 0; i < 2; i++) {
            int ml = row2 + i;
            float cr = Csm[ml * CSTRIDE + tx]      + Csm[64 * CSTRIDE + ml * CSTRIDE + tx];
            float cz = Csm[ml * CSTRIDE + 16 + tx] + Csm[64 * CSTRIDE + ml * CSTRIDE + 16 + tx];
            float cn = Csm[ml * CSTRIDE + 32 + tx] + Csm[64 * CSTRIDE + ml * CSTRIDE + 32 + tx];

            float r = 1.0f / (1.0f + expf(-(xr[i] + cr + bb0)));
            float z = 1.0f / (1.0f + expf(-(xz[i] + cz + bb1)));
            float n = tanhf(xn[i] + r * (cn + bb2));

            float hnew = (1.0f - z) * n + z * hreg[i];
            hreg[i] = hnew;
            Hsm[ml * HSTRIDE + tx] = hnew;

            if (t == T_ - 1) {
                g_hT[(size_t)(m0 + ml) * H_ + j] = hnew;
            }
        }
        __syncthreads();

        if (t < T_ - 1) {
            pack_hfrag(Hsm, mt, jt, t, tid);
#pragma unroll
            for (int i = 0; i < 2; i++) {
                size_t xb = ((size_t)(m0 + row2 + i) * T_ + (t + 1)) * G3H + j;
                xr[i] = g_xg[xb]; xz[i] = g_xg[xb + H_]; xn[i] = g_xg[xb + 2 * H_];
            }
            group_barrier(mt);
        }
    }
}

// ---------------------------------------------------------------------------
// Head: out = relu(relu(hT) @ fc1^T + b1) @ fc2^T + b2
// grid = 256 (batch), 512 threads. Warp-per-output with coalesced float4 loads.
// ---------------------------------------------------------------------------
__global__ void __launch_bounds__(512) head_kernel(
    const float* __restrict__ w1, const float* __restrict__ b1,
    const float* __restrict__ w2, const float* __restrict__ b2,
    float* __restrict__ out)
{
    __shared__ float sh[H_];
    __shared__ float s1[128];
    const int b = blockIdx.x;
    const int tid = threadIdx.x;
    const int w = tid >> 5, lane = tid & 31;

    sh[tid] = fmaxf(g_hT[(size_t)b * H_ + tid], 0.0f);
    __syncthreads();

    // fc1: warp w handles outputs w*8 .. w*8+7
#pragma unroll
    for (int oo = 0; oo < 8; oo++) {
        int o = w * 8 + oo;
        const float* wr = w1 + (size_t)o * H_;
        float acc = 0.f;
#pragma unroll
        for (int c = 0; c < 4; c++) {
            int k = c * 128 + lane * 4;
            float4 wv = *(const float4*)(wr + k);
            float4 hv = *(const float4*)(&sh[k]);
            acc += wv.x * hv.x + wv.y * hv.y + wv.z * hv.z + wv.w * hv.w;
        }
#pragma unroll
        for (int off = 16; off; off >>= 1)
            acc += __shfl_down_sync(0xFFFFFFFFu, acc, off);
        if (lane == 0) s1[o] = fmaxf(acc + b1[o], 0.0f);
    }
    __syncthreads();

    // fc2: warps 0..9 each compute one class output
    if (w < 10) {
        const float* wr = w2 + (size_t)w * 128;
        float acc = 0.f;
#pragma unroll
        for (int c = 0; c < 4; c++) {
            int k = lane + c * 32;
            acc += s1[k] * wr[k];
        }
#pragma unroll
        for (int off = 16; off; off >>= 1)
            acc += __shfl_down_sync(0xFFFFFFFFu, acc, off);
        if (lane == 0) out[(size_t)b * 10 + w] = acc + b2[w];
    }
}

// ---------------------------------------------------------------------------
// Launch
// ---------------------------------------------------------------------------
extern "C" void kernel_launch(void* const* d_in, const int* in_sizes, int n_in,
                              void* d_out, int out_size)
{
    const float* x    = (const float*)d_in[0];
    const float* Wih0 = (const float*)d_in[1];
    const float* Whh0 = (const float*)d_in[2];
    const float* bih0 = (const float*)d_in[3];
    const float* bhh0 = (const float*)d_in[4];
    const float* Wih1 = (const float*)d_in[5];
    const float* Whh1 = (const float*)d_in[6];
    const float* bih1 = (const float*)d_in[7];
    const float* bhh1 = (const float*)d_in[8];
    const float* fc1w = (const float*)d_in[9];
    const float* fc1b = (const float*)d_in[10];
    const float* fc2w = (const float*)d_in[11];
    const float* fc2b = (const float*)d_in[12];
    float* out = (float*)d_out;

    float* xg_ptr = nullptr;
    cudaGetSymbolAddress((void**)&xg_ptr, g_xg);

    const int rec0_smem = 12 * 32 * 32 * 16 + (64 * CSTRIDE + 64 * HSTRIDE) * 4;       // 213760
    const int rec1_smem = 6 * 32 * 32 * 16 + (2 * 64 * CSTRIDE + 64 * HSTRIDE) * 4;    // 128256
    cudaFuncSetAttribute((const void*)gru_rec0_fused_kernel,
                         cudaFuncAttributeMaxDynamicSharedMemorySize, rec0_smem);
    cudaFuncSetAttribute((const void*)gru_rec1_kernel,
                         cudaFuncAttributeMaxDynamicSharedMemorySize, rec1_smem);

    dim3 gemm_grid(G3H / 128, BT / 128);  // (12, 512)

    // Phase 1: xg0 = x @ W_ih0^T + b_ih0   (K = 128)
    gemm_tf32_kernel<<<gemm_grid, 256>>>(x, Wih0, bih0, D_, xg_ptr);

    // Phase 2: fused layer-0 recurrence + layer-1 input projection
    gru_rec0_fused_kernel<<<128, 512, rec0_smem>>>(Whh0, bhh0, Wih1, bih1);

    // Phase 3: layer-1 recurrence
    gru_rec1_kernel<<<128, 512, rec1_smem>>>(Whh1, bhh1);

    // Phase 4: MLP head
    head_kernel<<<B_, 512>>>(fc1w, fc1b, fc2w, fc2b, out);
}